// round 7
// baseline (speedup 1.0000x reference)
#include <cuda_runtime.h>
#include <math.h>
#include <stdint.h>

// ---------------------------------------------------------------------------
// Problem constants
// ---------------------------------------------------------------------------
#define BD      2
#define LSEQ    2048
#define DMODEL  2048
#define NH      16
#define HD      128
#define ROWS    (BD * LSEQ)      // 4096

// ---------------------------------------------------------------------------
// Scratch (device globals -- no allocation allowed)
// ---------------------------------------------------------------------------
__device__ float g_qkv[ROWS * 3 * DMODEL];                 // fp32
__device__ float g_x2 [ROWS * DMODEL];
__device__ float g_o  [ROWS * DMODEL];
__device__ float g_p  [(size_t)ROWS * 8 * DMODEL];

// quantized activations (reused across stages; max row width 8192)
__device__ char  g_a1[(size_t)ROWS * 8 * DMODEL];
__device__ char  g_a0[(size_t)ROWS * 8 * DMODEL];
__device__ float g_sa[ROWS];

// quantized weights, transposed to [N, K]
__device__ char g_w1qkv[3 * DMODEL * DMODEL], g_w0qkv[3 * DMODEL * DMODEL];
__device__ char g_w1o  [DMODEL * DMODEL],     g_w0o  [DMODEL * DMODEL];
__device__ char g_w1p  [(size_t)8 * DMODEL * DMODEL], g_w0p[(size_t)8 * DMODEL * DMODEL];
__device__ char g_w1ff [(size_t)4 * DMODEL * DMODEL], g_w0ff[(size_t)4 * DMODEL * DMODEL];
__device__ float g_sqkv[3 * DMODEL], g_so[DMODEL], g_sp[8 * DMODEL], g_sff[DMODEL];

// ---------------------------------------------------------------------------
// Helpers
// ---------------------------------------------------------------------------
__device__ __forceinline__ uint32_t smem_u32(const void* p) {
    uint32_t a;
    asm("{ .reg .u64 t; cvta.to.shared.u64 t, %1; cvt.u32.u64 %0, t; }"
        : "=r"(a) : "l"(p));
    return a;
}
__device__ __forceinline__ void cp16(uint32_t dst, const void* src) {
    asm volatile("cp.async.cg.shared.global [%0], [%1], 16;" :: "r"(dst), "l"(src));
}
__device__ __forceinline__ void ldsm_x4(uint32_t* r, uint32_t a) {
    asm volatile("ldmatrix.sync.aligned.m8n8.x4.shared.b16 {%0,%1,%2,%3}, [%4];"
        : "=r"(r[0]), "=r"(r[1]), "=r"(r[2]), "=r"(r[3]) : "r"(a));
}
__device__ __forceinline__ void ldsm_x2(uint32_t* r, uint32_t a) {
    asm volatile("ldmatrix.sync.aligned.m8n8.x2.shared.b16 {%0,%1}, [%2];"
        : "=r"(r[0]), "=r"(r[1]) : "r"(a));
}
__device__ __forceinline__ void imma16832(int* d, const uint32_t* a, const uint32_t* b) {
    asm volatile("mma.sync.aligned.m16n8k32.row.col.s32.s8.s8.s32 "
        "{%0,%1,%2,%3}, {%4,%5,%6,%7}, {%8,%9}, {%0,%1,%2,%3};"
        : "+r"(d[0]), "+r"(d[1]), "+r"(d[2]), "+r"(d[3])
        : "r"(a[0]), "r"(a[1]), "r"(a[2]), "r"(a[3]), "r"(b[0]), "r"(b[1]));
}
// two-digit base-128 quantization: x/s = 128*h + l, h in [-127,127], l in [-64,64]
__device__ __forceinline__ void quant2(float q, char* h8, char* l8) {
    int h = __float2int_rn(q * 0.0078125f);
    int l = __float2int_rn(q - 128.0f * (float)h);
    *h8 = (char)h; *l8 = (char)l;
}

// ---------------------------------------------------------------------------
// int8x3 mma GEMM: C[M,N] = sA sB (128 A1+A0)(128 B1+B0)^T + bias (+res)
// CTA 128x128, 8 warps (2x4), warp tile 64x32, K-chunk 32 (one k32 mma step).
// 4-stage cp.async pipeline, 96KB smem, one syncthreads per chunk.
// smem pitch 48B -> conflict-free ldmatrix (banks 12r mod 32 distinct, r<8).
// ---------------------------------------------------------------------------
#define GK       32
#define QPITCH   48
#define ARR_B    6144            // 128 * 48
#define STAGE_B  24576           // A1, A0, B1, B0
#define NSTAGE   4
#define GSMEM    (NSTAGE * STAGE_B)   // 98304

__device__ __forceinline__ void q_load_chunk(
    uint32_t st, int c, int tid,
    const char* __restrict__ A1, const char* __restrict__ A0,
    const char* __restrict__ B1, const char* __restrict__ B0,
    int K, int m0, int n0)
{
    const int k0 = c * GK;
    #pragma unroll
    for (int i = 0; i < 4; i++) {
        int e   = tid + (i << 8);        // 0..1023
        int r   = e >> 1;                // 0..511
        int cc  = e & 1;                 // 16B half of 32B row
        int arr = r >> 7;                // 0..3
        int rr  = r & 127;
        uint32_t dst = st + (uint32_t)arr * ARR_B + (uint32_t)rr * QPITCH + cc * 16;
        const char* base = (arr == 0) ? A1 : (arr == 1) ? A0 : (arr == 2) ? B1 : B0;
        int rb = (arr < 2) ? m0 : n0;
        cp16(dst, base + (size_t)(rb + rr) * K + k0 + cc * 16);
    }
    asm volatile("cp.async.commit_group;" ::: "memory");
}

__global__ void __launch_bounds__(256)
gemm_i8(const char* __restrict__ A1, const char* __restrict__ A0,
        const float* __restrict__ sA,
        const char* __restrict__ B1, const char* __restrict__ B0,
        const float* __restrict__ sB,
        const float* __restrict__ bias, const float* __restrict__ res,
        float* __restrict__ C, int K, int N)
{
    extern __shared__ __align__(16) char sm_[];
    const uint32_t sb = smem_u32(sm_);
    const int tid  = threadIdx.x;
    const int lane = tid & 31;
    const int wid  = tid >> 5;
    const int wm   = wid >> 2;
    const int wn   = wid & 3;
    const int m0 = blockIdx.y << 7;
    const int n0 = blockIdx.x << 7;
    const int NC = K / GK;

    int acc1[4][4][4], accX[4][4][4];
    #pragma unroll
    for (int i = 0; i < 4; i++)
        #pragma unroll
        for (int j = 0; j < 4; j++)
            #pragma unroll
            for (int q = 0; q < 4; q++) { acc1[i][j][q] = 0; accX[i][j][q] = 0; }

    q_load_chunk(sb,               0, tid, A1, A0, B1, B0, K, m0, n0);
    q_load_chunk(sb + STAGE_B,     1, tid, A1, A0, B1, B0, K, m0, n0);
    q_load_chunk(sb + 2 * STAGE_B, 2, tid, A1, A0, B1, B0, K, m0, n0);

    // ldmatrix lane addressing (same 8x8-matrix mapping as validated bf16 kernel)
    const int rowA  = (lane & 7) + ((lane >> 3) & 1) * 8;
    const int kadA  = (lane >> 4) * 16;
    const uint32_t a_ld = (uint32_t)((wm * 64 + rowA) * QPITCH + kadA);
    const int rowB  = lane & 7;
    const int kadB  = ((lane >> 3) & 1) * 16;
    const uint32_t b_ld = (uint32_t)((wn * 32 + rowB) * QPITCH + kadB);

    for (int c = 0; c < NC; c++) {
        asm volatile("cp.async.wait_group 2;" ::: "memory");
        __syncthreads();

        if (c + 3 < NC)
            q_load_chunk(sb + (uint32_t)((c + 3) & 3) * STAGE_B, c + 3, tid,
                         A1, A0, B1, B0, K, m0, n0);

        const uint32_t st = sb + (uint32_t)(c & 3) * STAGE_B;

        uint32_t a1[4][4], b1[4][2];
        #pragma unroll
        for (int mt = 0; mt < 4; mt++)
            ldsm_x4(a1[mt], st + a_ld + mt * (16 * QPITCH));
        #pragma unroll
        for (int nt = 0; nt < 4; nt++)
            ldsm_x2(b1[nt], st + 2 * ARR_B + b_ld + nt * (8 * QPITCH));

        // pass 1: A1 x B1 -> acc1
        #pragma unroll
        for (int mt = 0; mt < 4; mt++)
            #pragma unroll
            for (int nt = 0; nt < 4; nt++)
                imma16832(acc1[mt][nt], a1[mt], b1[nt]);

        // pass 2: A1 x B0 -> accX
        uint32_t b0[4][2];
        #pragma unroll
        for (int nt = 0; nt < 4; nt++)
            ldsm_x2(b0[nt], st + 3 * ARR_B + b_ld + nt * (8 * QPITCH));
        #pragma unroll
        for (int mt = 0; mt < 4; mt++)
            #pragma unroll
            for (int nt = 0; nt < 4; nt++)
                imma16832(accX[mt][nt], a1[mt], b0[nt]);

        // pass 3: A0 x B1 -> accX
        uint32_t a0[4][4];
        #pragma unroll
        for (int mt = 0; mt < 4; mt++)
            ldsm_x4(a0[mt], st + ARR_B + a_ld + mt * (16 * QPITCH));
        #pragma unroll
        for (int mt = 0; mt < 4; mt++)
            #pragma unroll
            for (int nt = 0; nt < 4; nt++)
                imma16832(accX[mt][nt], a0[mt], b1[nt]);
    }

    // epilogue: C = sA*sB*(16384*acc1 + 128*accX) + bias (+res)
    #pragma unroll
    for (int mt = 0; mt < 4; mt++) {
        const int rg = m0 + wm * 64 + mt * 16 + (lane >> 2);
        const float sa0 = sA[rg], sa1 = sA[rg + 8];
        #pragma unroll
        for (int nt = 0; nt < 4; nt++) {
            const int cg = n0 + wn * 32 + nt * 8 + (lane & 3) * 2;
            float2 sbv = *(const float2*)(sB + cg);
            float2 bv  = *(const float2*)(bias + cg);
            float v0 = sa0 * sbv.x * (16384.f * (float)acc1[mt][nt][0] + 128.f * (float)accX[mt][nt][0]);
            float v1 = sa0 * sbv.y * (16384.f * (float)acc1[mt][nt][1] + 128.f * (float)accX[mt][nt][1]);
            float v2 = sa1 * sbv.x * (16384.f * (float)acc1[mt][nt][2] + 128.f * (float)accX[mt][nt][2]);
            float v3 = sa1 * sbv.y * (16384.f * (float)acc1[mt][nt][3] + 128.f * (float)accX[mt][nt][3]);
            float2 o0, o1;
            o0.x = v0 + bv.x; o0.y = v1 + bv.y;
            o1.x = v2 + bv.x; o1.y = v3 + bv.y;
            if (res) {
                float2 r0 = *(const float2*)(res + (size_t)rg * N + cg);
                float2 r1 = *(const float2*)(res + (size_t)(rg + 8) * N + cg);
                o0.x += r0.x; o0.y += r0.y;
                o1.x += r1.x; o1.y += r1.y;
            }
            *(float2*)(C + (size_t)rg * N + cg)       = o0;
            *(float2*)(C + (size_t)(rg + 8) * N + cg) = o1;
        }
    }
}

// ---------------------------------------------------------------------------
// Column-max of W[K,N] -> per-output-column scale
// ---------------------------------------------------------------------------
__global__ void __launch_bounds__(256)
colmax_kernel(const float* __restrict__ W, float* __restrict__ s, int Kd, int Nd)
{
    __shared__ float red[8][32];
    const int nl = threadIdx.x & 31;
    const int ks = threadIdx.x >> 5;
    const int n  = blockIdx.x * 32 + nl;
    const int kpart = Kd >> 3;
    float m = 0.f;
    const float* p = W + (size_t)ks * kpart * Nd + n;
    #pragma unroll 4
    for (int k = 0; k < kpart; k++) m = fmaxf(m, fabsf(p[(size_t)k * Nd]));
    red[ks][nl] = m;
    __syncthreads();
    if (ks == 0) {
        float mm = red[0][nl];
        #pragma unroll
        for (int i = 1; i < 8; i++) mm = fmaxf(mm, red[i][nl]);
        s[n] = fmaxf(mm, 1e-30f) * (1.0f / 16256.0f);
    }
}

// ---------------------------------------------------------------------------
// Transpose + two-digit quantize: W[K,N] fp32 -> B1,B0 [N,K] s8
// ---------------------------------------------------------------------------
__global__ void __launch_bounds__(256)
transp_quant(const float* __restrict__ W, const float* __restrict__ sB,
             char* __restrict__ B1, char* __restrict__ B0, int Kd, int Nd)
{
    __shared__ float t[32][33];
    const int n0 = blockIdx.x * 32, k0 = blockIdx.y * 32;
    const int tx = threadIdx.x & 31, ty = threadIdx.x >> 5;
    #pragma unroll
    for (int i = 0; i < 4; i++) {
        int kk = ty + i * 8;
        t[kk][tx] = W[(size_t)(k0 + kk) * Nd + n0 + tx];
    }
    __syncthreads();
    #pragma unroll
    for (int i = 0; i < 4; i++) {
        int nn = ty + i * 8;
        float q = t[tx][nn] / sB[n0 + nn];
        size_t o = (size_t)(n0 + nn) * Kd + k0 + tx;
        char h, l; quant2(q, &h, &l);
        B1[o] = h; B0[o] = l;
    }
}

// ---------------------------------------------------------------------------
// RMSNorm + row quantize (row width 2048)
// ---------------------------------------------------------------------------
__global__ void __launch_bounds__(256)
rmsnorm_quant(const float* __restrict__ in, const float* __restrict__ g,
              char* __restrict__ A1, char* __restrict__ A0, float* __restrict__ sA)
{
    __shared__ float red[8], redm[8];
    const int row = blockIdx.x;
    const int tid = threadIdx.x;
    const float4* inr = (const float4*)(in + (size_t)row * DMODEL);
    float4 v0 = inr[tid], v1 = inr[tid + 256];
    float ss = v0.x*v0.x + v0.y*v0.y + v0.z*v0.z + v0.w*v0.w
             + v1.x*v1.x + v1.y*v1.y + v1.z*v1.z + v1.w*v1.w;
    #pragma unroll
    for (int o = 16; o; o >>= 1) ss += __shfl_xor_sync(0xffffffffu, ss, o);
    if ((tid & 31) == 0) red[tid >> 5] = ss;
    __syncthreads();
    float tot = red[0]+red[1]+red[2]+red[3]+red[4]+red[5]+red[6]+red[7];
    float rs = rsqrtf(tot * (1.0f / DMODEL) + 1e-8f);

    const float4* gr = (const float4*)g;
    float4 ga = gr[tid], gb = gr[tid + 256];
    float y[8] = { v0.x*rs*ga.x, v0.y*rs*ga.y, v0.z*rs*ga.z, v0.w*rs*ga.w,
                   v1.x*rs*gb.x, v1.y*rs*gb.y, v1.z*rs*gb.z, v1.w*rs*gb.w };
    float mx = 0.f;
    #pragma unroll
    for (int i = 0; i < 8; i++) mx = fmaxf(mx, fabsf(y[i]));
    #pragma unroll
    for (int o = 16; o; o >>= 1) mx = fmaxf(mx, __shfl_xor_sync(0xffffffffu, mx, o));
    if ((tid & 31) == 0) redm[tid >> 5] = mx;
    __syncthreads();
    float mm = fmaxf(fmaxf(fmaxf(redm[0],redm[1]),fmaxf(redm[2],redm[3])),
                     fmaxf(fmaxf(redm[4],redm[5]),fmaxf(redm[6],redm[7])));
    float s = fmaxf(mm, 1e-30f) * (1.0f / 16256.0f);
    if (tid == 0) sA[row] = s;
    float invs = 1.0f / s;

    char h[8], l[8];
    #pragma unroll
    for (int i = 0; i < 8; i++) quant2(y[i] * invs, &h[i], &l[i]);
    char* a1r = A1 + (size_t)row * DMODEL;
    char* a0r = A0 + (size_t)row * DMODEL;
    *(char4*)(a1r + tid * 4)         = make_char4(h[0], h[1], h[2], h[3]);
    *(char4*)(a1r + (tid + 256) * 4) = make_char4(h[4], h[5], h[6], h[7]);
    *(char4*)(a0r + tid * 4)         = make_char4(l[0], l[1], l[2], l[3]);
    *(char4*)(a0r + (tid + 256) * 4) = make_char4(l[4], l[5], l[6], l[7]);
}

// ---------------------------------------------------------------------------
// Row quantize a fp32 [*, 2048] matrix
// ---------------------------------------------------------------------------
__global__ void __launch_bounds__(256)
rowquant2048(const float* __restrict__ X,
             char* __restrict__ A1, char* __restrict__ A0, float* __restrict__ sA)
{
    __shared__ float redm[8];
    const int row = blockIdx.x;
    const int tid = threadIdx.x;
    const float4* xr = (const float4*)(X + (size_t)row * DMODEL);
    float4 v0 = xr[tid], v1 = xr[tid + 256];
    float y[8] = { v0.x, v0.y, v0.z, v0.w, v1.x, v1.y, v1.z, v1.w };
    float mx = 0.f;
    #pragma unroll
    for (int i = 0; i < 8; i++) mx = fmaxf(mx, fabsf(y[i]));
    #pragma unroll
    for (int o = 16; o; o >>= 1) mx = fmaxf(mx, __shfl_xor_sync(0xffffffffu, mx, o));
    if ((tid & 31) == 0) redm[tid >> 5] = mx;
    __syncthreads();
    float mm = fmaxf(fmaxf(fmaxf(redm[0],redm[1]),fmaxf(redm[2],redm[3])),
                     fmaxf(fmaxf(redm[4],redm[5]),fmaxf(redm[6],redm[7])));
    float s = fmaxf(mm, 1e-30f) * (1.0f / 16256.0f);
    if (tid == 0) sA[row] = s;
    float invs = 1.0f / s;
    char h[8], l[8];
    #pragma unroll
    for (int i = 0; i < 8; i++) quant2(y[i] * invs, &h[i], &l[i]);
    char* a1r = A1 + (size_t)row * DMODEL;
    char* a0r = A0 + (size_t)row * DMODEL;
    *(char4*)(a1r + tid * 4)         = make_char4(h[0], h[1], h[2], h[3]);
    *(char4*)(a1r + (tid + 256) * 4) = make_char4(h[4], h[5], h[6], h[7]);
    *(char4*)(a0r + tid * 4)         = make_char4(l[0], l[1], l[2], l[3]);
    *(char4*)(a0r + (tid + 256) * 4) = make_char4(l[4], l[5], l[6], l[7]);
}

// ---------------------------------------------------------------------------
// SwiGLU + row quantize (output row width 8192)
// ---------------------------------------------------------------------------
__global__ void __launch_bounds__(256)
swiglu_rowquant(const float* __restrict__ P,
                char* __restrict__ A1, char* __restrict__ A0, float* __restrict__ sA)
{
    __shared__ float redm[8];
    const int row = blockIdx.x;
    const int tid = threadIdx.x;
    const float* pr = P + (size_t)row * 16384;
    float f[32];
    float mx = 0.f;
    #pragma unroll
    for (int i = 0; i < 8; i++) {
        int idx = (tid + i * 256) * 4;
        float4 gt = *(const float4*)(pr + idx);
        float4 vl = *(const float4*)(pr + 8192 + idx);
        f[i*4+0] = gt.x / (1.f + __expf(-gt.x)) * vl.x;
        f[i*4+1] = gt.y / (1.f + __expf(-gt.y)) * vl.y;
        f[i*4+2] = gt.z / (1.f + __expf(-gt.z)) * vl.z;
        f[i*4+3] = gt.w / (1.f + __expf(-gt.w)) * vl.w;
        mx = fmaxf(mx, fmaxf(fmaxf(fabsf(f[i*4]), fabsf(f[i*4+1])),
                             fmaxf(fabsf(f[i*4+2]), fabsf(f[i*4+3]))));
    }
    #pragma unroll
    for (int o = 16; o; o >>= 1) mx = fmaxf(mx, __shfl_xor_sync(0xffffffffu, mx, o));
    if ((tid & 31) == 0) redm[tid >> 5] = mx;
    __syncthreads();
    float mm = fmaxf(fmaxf(fmaxf(redm[0],redm[1]),fmaxf(redm[2],redm[3])),
                     fmaxf(fmaxf(redm[4],redm[5]),fmaxf(redm[6],redm[7])));
    float s = fmaxf(mm, 1e-30f) * (1.0f / 16256.0f);
    if (tid == 0) sA[row] = s;
    float invs = 1.0f / s;
    char* a1r = A1 + (size_t)row * 8192;
    char* a0r = A0 + (size_t)row * 8192;
    #pragma unroll
    for (int i = 0; i < 8; i++) {
        int idx = (tid + i * 256) * 4;
        char h[4], l[4];
        #pragma unroll
        for (int q = 0; q < 4; q++) quant2(f[i*4+q] * invs, &h[q], &l[q]);
        *(char4*)(a1r + idx) = make_char4(h[0], h[1], h[2], h[3]);
        *(char4*)(a0r + idx) = make_char4(l[0], l[1], l[2], l[3]);
    }
}

// ---------------------------------------------------------------------------
// RoPE (in place on q,k of qkv)
// ---------------------------------------------------------------------------
__global__ void __launch_bounds__(256)
rope_kernel(float* __restrict__ qkv)
{
    const long idx = (long)blockIdx.x * 256 + threadIdx.x;
    const int  i   = (int)(idx & 63);
    const int  h   = (int)((idx >> 6) & 15);
    const long bl  = idx >> 10;
    const long l   = bl & 2047;

    float freq = expf(-(float)i * 0.14391156642875464f);
    float angle = (float)l * freq;
    float s, c;
    sincosf(angle, &s, &c);

    float* qp = qkv + bl * (3 * DMODEL) + h * HD + i;
    float* kp = qp + DMODEL;
    float q1 = qp[0], q2 = qp[64];
    float k1 = kp[0], k2 = kp[64];
    qp[0]  = q1 * c - q2 * s;
    qp[64] = q2 * c + q1 * s;
    kp[0]  = k1 * c - k2 * s;
    kp[64] = k2 * c + k1 * s;
}

// ---------------------------------------------------------------------------
// Flash attention (causal, fp32), fp32 output
// ---------------------------------------------------------------------------
#define ATT_BM   64
#define ATT_BN   64
#define QSTRIDE  132
#define PSTRIDE  68
#define ATT_SMEM ((3 * ATT_BM * QSTRIDE + ATT_BM * PSTRIDE) * (int)sizeof(float))

__global__ void __launch_bounds__(256)
attn_kernel(const float* __restrict__ qkv, float* __restrict__ O)
{
    extern __shared__ float smem[];
    float* sQ = smem;
    float* sK = sQ + ATT_BM * QSTRIDE;
    float* sV = sK + ATT_BN * QSTRIDE;
    float* sP = sV + ATT_BN * QSTRIDE;

    const int bh = blockIdx.y;
    const int b  = bh >> 4;
    const int h  = bh & 15;
    const int qi = gridDim.x - 1 - blockIdx.x;
    const int q0 = qi * ATT_BM;
    const int tid = threadIdx.x;
    const int r  = tid >> 2;
    const int qd = tid & 3;

    const float* qbase = qkv + (size_t)(b * LSEQ) * (3 * DMODEL) + h * HD;
    const float* kbase = qbase + DMODEL;
    const float* vbase = qbase + 2 * DMODEL;

    for (int i = tid; i < ATT_BM * 32; i += 256) {
        int row = i >> 5, c4 = (i & 31) << 2;
        *(float4*)(sQ + row * QSTRIDE + c4) =
            *(const float4*)(qbase + (size_t)(q0 + row) * (3 * DMODEL) + c4);
    }

    float accO[32];
    #pragma unroll
    for (int i = 0; i < 32; i++) accO[i] = 0.f;
    float mrow = -1e30f, lrow = 0.f;
    const int qg = q0 + r;
    const float scale = 0.088388347648318447f;

    const int nk = qi + 1;
    for (int kt = 0; kt < nk; kt++) {
        const int k0 = kt * ATT_BN;
        __syncthreads();
        for (int i = tid; i < ATT_BN * 32; i += 256) {
            int row = i >> 5, c4 = (i & 31) << 2;
            size_t goff = (size_t)(k0 + row) * (3 * DMODEL) + c4;
            *(float4*)(sK + row * QSTRIDE + c4) = *(const float4*)(kbase + goff);
            *(float4*)(sV + row * QSTRIDE + c4) = *(const float4*)(vbase + goff);
        }
        __syncthreads();

        float s[16];
        #pragma unroll
        for (int jj = 0; jj < 16; jj++) s[jj] = 0.f;
        const float* qr = sQ + r * QSTRIDE;
        #pragma unroll 2
        for (int d = 0; d < HD; d += 4) {
            float4 qv = *(const float4*)(qr + d);
            #pragma unroll
            for (int jj = 0; jj < 16; jj++) {
                float4 kv = *(const float4*)(sK + (qd + (jj << 2)) * QSTRIDE + d);
                s[jj] = fmaf(qv.x, kv.x, s[jj]);
                s[jj] = fmaf(qv.y, kv.y, s[jj]);
                s[jj] = fmaf(qv.z, kv.z, s[jj]);
                s[jj] = fmaf(qv.w, kv.w, s[jj]);
            }
        }

        float tmax = -1e30f;
        #pragma unroll
        for (int jj = 0; jj < 16; jj++) {
            int jgl = k0 + qd + (jj << 2);
            s[jj] = (jgl <= qg) ? s[jj] * scale : -1e30f;
            tmax = fmaxf(tmax, s[jj]);
        }
        tmax = fmaxf(tmax, __shfl_xor_sync(0xffffffffu, tmax, 1));
        tmax = fmaxf(tmax, __shfl_xor_sync(0xffffffffu, tmax, 2));

        float mnew = fmaxf(mrow, tmax);
        float corr = __expf(mrow - mnew);
        float psum = 0.f;
        #pragma unroll
        for (int jj = 0; jj < 16; jj++) {
            float p = __expf(s[jj] - mnew);
            s[jj] = p;
            psum += p;
        }
        psum += __shfl_xor_sync(0xffffffffu, psum, 1);
        psum += __shfl_xor_sync(0xffffffffu, psum, 2);
        lrow = lrow * corr + psum;
        mrow = mnew;
        #pragma unroll
        for (int i = 0; i < 32; i++) accO[i] *= corr;

        #pragma unroll
        for (int jj = 0; jj < 16; jj++)
            sP[r * PSTRIDE + qd + (jj << 2)] = s[jj];
        __syncthreads();

        const float* prow = sP + r * PSTRIDE;
        #pragma unroll 4
        for (int j = 0; j < ATT_BN; j++) {
            float p = prow[j];
            const float4* vr = (const float4*)(sV + j * QSTRIDE + (qd << 5));
            #pragma unroll
            for (int cc = 0; cc < 8; cc++) {
                float4 vv = vr[cc];
                accO[cc * 4 + 0] = fmaf(p, vv.x, accO[cc * 4 + 0]);
                accO[cc * 4 + 1] = fmaf(p, vv.y, accO[cc * 4 + 1]);
                accO[cc * 4 + 2] = fmaf(p, vv.z, accO[cc * 4 + 2]);
                accO[cc * 4 + 3] = fmaf(p, vv.w, accO[cc * 4 + 3]);
            }
        }
    }

    float inv = 1.f / lrow;
    float* orow = O + (size_t)(b * LSEQ + qg) * DMODEL + h * HD + (qd << 5);
    #pragma unroll
    for (int cc = 0; cc < 8; cc++) {
        float4 w;
        w.x = accO[cc * 4 + 0] * inv;
        w.y = accO[cc * 4 + 1] * inv;
        w.z = accO[cc * 4 + 2] * inv;
        w.w = accO[cc * 4 + 3] * inv;
        *(float4*)(orow + cc * 4) = w;
    }
}

// ---------------------------------------------------------------------------
// Host launcher
// ---------------------------------------------------------------------------
extern "C" void kernel_launch(void* const* d_in, const int* in_sizes, int n_in,
                              void* d_out, int out_size)
{
    const float* x    = (const float*)d_in[0];
    const float* Wqkv = (const float*)d_in[1];
    const float* bqkv = (const float*)d_in[2];
    const float* Wo   = (const float*)d_in[3];
    const float* bo   = (const float*)d_in[4];
    const float* g1   = (const float*)d_in[5];
    const float* g2   = (const float*)d_in[6];
    const float* Wp   = (const float*)d_in[7];
    const float* bp   = (const float*)d_in[8];
    const float* Wff  = (const float*)d_in[9];
    const float* bff  = (const float*)d_in[10];
    float* out = (float*)d_out;

    float *p_qkv, *p_x2, *p_o, *p_p, *p_sa;
    char *p_a1, *p_a0;
    char *p_w1qkv, *p_w0qkv, *p_w1o, *p_w0o, *p_w1p, *p_w0p, *p_w1ff, *p_w0ff;
    float *p_sqkv, *p_so, *p_sp, *p_sff;
    cudaGetSymbolAddress((void**)&p_qkv, g_qkv);
    cudaGetSymbolAddress((void**)&p_x2,  g_x2);
    cudaGetSymbolAddress((void**)&p_o,   g_o);
    cudaGetSymbolAddress((void**)&p_p,   g_p);
    cudaGetSymbolAddress((void**)&p_a1,  g_a1);
    cudaGetSymbolAddress((void**)&p_a0,  g_a0);
    cudaGetSymbolAddress((void**)&p_sa,  g_sa);
    cudaGetSymbolAddress((void**)&p_w1qkv, g_w1qkv); cudaGetSymbolAddress((void**)&p_w0qkv, g_w0qkv);
    cudaGetSymbolAddress((void**)&p_w1o,   g_w1o);   cudaGetSymbolAddress((void**)&p_w0o,   g_w0o);
    cudaGetSymbolAddress((void**)&p_w1p,   g_w1p);   cudaGetSymbolAddress((void**)&p_w0p,   g_w0p);
    cudaGetSymbolAddress((void**)&p_w1ff,  g_w1ff);  cudaGetSymbolAddress((void**)&p_w0ff,  g_w0ff);
    cudaGetSymbolAddress((void**)&p_sqkv,  g_sqkv);  cudaGetSymbolAddress((void**)&p_so,    g_so);
    cudaGetSymbolAddress((void**)&p_sp,    g_sp);    cudaGetSymbolAddress((void**)&p_sff,   g_sff);

    cudaFuncSetAttribute(attn_kernel, cudaFuncAttributeMaxDynamicSharedMemorySize, ATT_SMEM);
    cudaFuncSetAttribute(gemm_i8,     cudaFuncAttributeMaxDynamicSharedMemorySize, GSMEM);

    // weight scales + transpose/quantize
    colmax_kernel<<<3 * DMODEL / 32, 256>>>(Wqkv, p_sqkv, DMODEL, 3 * DMODEL);
    colmax_kernel<<<DMODEL / 32, 256>>>(Wo, p_so, DMODEL, DMODEL);
    colmax_kernel<<<8 * DMODEL / 32, 256>>>(Wp, p_sp, DMODEL, 8 * DMODEL);
    colmax_kernel<<<DMODEL / 32, 256>>>(Wff, p_sff, 4 * DMODEL, DMODEL);
    transp_quant<<<dim3(3 * DMODEL / 32, DMODEL / 32), 256>>>(Wqkv, p_sqkv, p_w1qkv, p_w0qkv, DMODEL, 3 * DMODEL);
    transp_quant<<<dim3(DMODEL / 32, DMODEL / 32), 256>>>(Wo, p_so, p_w1o, p_w0o, DMODEL, DMODEL);
    transp_quant<<<dim3(8 * DMODEL / 32, DMODEL / 32), 256>>>(Wp, p_sp, p_w1p, p_w0p, DMODEL, 8 * DMODEL);
    transp_quant<<<dim3(DMODEL / 32, 4 * DMODEL / 32), 256>>>(Wff, p_sff, p_w1ff, p_w0ff, 4 * DMODEL, DMODEL);

    // 1. pre-norm + quantize
    rmsnorm_quant<<<ROWS, 256>>>(x, g1, p_a1, p_a0, p_sa);

    // 2. QKV projection
    gemm_i8<<<dim3(3 * DMODEL / 128, ROWS / 128), 256, GSMEM>>>(
        p_a1, p_a0, p_sa, p_w1qkv, p_w0qkv, p_sqkv, bqkv, nullptr, p_qkv, DMODEL, 3 * DMODEL);

    // 3. RoPE
    rope_kernel<<<(ROWS * NH * 64) / 256, 256>>>(p_qkv);

    // 4. causal flash attention (fp32)
    attn_kernel<<<dim3(LSEQ / ATT_BM, BD * NH), 256, ATT_SMEM>>>(p_qkv, p_o);

    // 5. quantize O, output projection + residual
    rowquant2048<<<ROWS, 256>>>(p_o, p_a1, p_a0, p_sa);
    gemm_i8<<<dim3(DMODEL / 128, ROWS / 128), 256, GSMEM>>>(
        p_a1, p_a0, p_sa, p_w1o, p_w0o, p_so, bo, x, p_x2, DMODEL, DMODEL);

    // 6. second pre-norm + quantize
    rmsnorm_quant<<<ROWS, 256>>>(p_x2, g2, p_a1, p_a0, p_sa);

    // 7. FFN up-projection
    gemm_i8<<<dim3(8 * DMODEL / 128, ROWS / 128), 256, GSMEM>>>(
        p_a1, p_a0, p_sa, p_w1p, p_w0p, p_sp, bp, nullptr, p_p, DMODEL, 8 * DMODEL);

    // 8. SwiGLU + quantize
    swiglu_rowquant<<<ROWS, 256>>>(p_p, p_a1, p_a0, p_sa);

    // 9. FFN down-projection + residual -> output
    gemm_i8<<<dim3(DMODEL / 128, ROWS / 128), 256, GSMEM>>>(
        p_a1, p_a0, p_sa, p_w1ff, p_w0ff, p_sff, bff, p_x2, out, 4 * DMODEL, DMODEL);
}

// round 8
// speedup vs baseline: 1.6860x; 1.6860x over previous
#include <cuda_runtime.h>
#include <cuda_fp16.h>
#include <math.h>
#include <stdint.h>

// ---------------------------------------------------------------------------
// Problem constants
// ---------------------------------------------------------------------------
#define BD      2
#define LSEQ    2048
#define DMODEL  2048
#define NH      16
#define HD      128
#define ROWS    (BD * LSEQ)      // 4096

// ---------------------------------------------------------------------------
// Scratch (device globals -- no allocation allowed)
// ---------------------------------------------------------------------------
__device__ float g_qkv[ROWS * 3 * DMODEL];                 // 96 MB fp32
__device__ float g_x2 [ROWS * DMODEL];                     // 32 MB fp32
__device__ float g_p  [(size_t)ROWS * 8 * DMODEL];         // 256 MB fp32

__device__ __half g_xnh[ROWS * DMODEL], g_xnl[ROWS * DMODEL];
__device__ __half g_oh [ROWS * DMODEL], g_ol [ROWS * DMODEL];
__device__ __half g_ffh[(size_t)ROWS * 4 * DMODEL], g_ffl[(size_t)ROWS * 4 * DMODEL];
// transposed weights [N, K] fp16 hi/lo
__device__ __half g_wqkvh[3 * DMODEL * DMODEL], g_wqkvl[3 * DMODEL * DMODEL];
__device__ __half g_woh  [DMODEL * DMODEL],     g_wol  [DMODEL * DMODEL];
__device__ __half g_wph  [(size_t)8 * DMODEL * DMODEL], g_wpl[(size_t)8 * DMODEL * DMODEL];
__device__ __half g_wffh [(size_t)4 * DMODEL * DMODEL], g_wffl[(size_t)4 * DMODEL * DMODEL];

// ---------------------------------------------------------------------------
// Helpers
// ---------------------------------------------------------------------------
__device__ __forceinline__ uint32_t smem_u32(const void* p) {
    uint32_t a;
    asm("{ .reg .u64 t; cvta.to.shared.u64 t, %1; cvt.u32.u64 %0, t; }"
        : "=r"(a) : "l"(p));
    return a;
}
__device__ __forceinline__ void cp16(uint32_t dst, const void* src) {
    asm volatile("cp.async.cg.shared.global [%0], [%1], 16;" :: "r"(dst), "l"(src));
}
__device__ __forceinline__ void ldsm_x4(uint32_t* r, uint32_t a) {
    asm volatile("ldmatrix.sync.aligned.m8n8.x4.shared.b16 {%0,%1,%2,%3}, [%4];"
        : "=r"(r[0]), "=r"(r[1]), "=r"(r[2]), "=r"(r[3]) : "r"(a));
}
__device__ __forceinline__ void ldsm_x2(uint32_t* r, uint32_t a) {
    asm volatile("ldmatrix.sync.aligned.m8n8.x2.shared.b16 {%0,%1}, [%2];"
        : "=r"(r[0]), "=r"(r[1]) : "r"(a));
}
// fp16 inputs, fp32 accumulator (main pass)
__device__ __forceinline__ void mma_f32(float* d, const uint32_t* a, const uint32_t* b) {
    asm volatile("mma.sync.aligned.m16n8k16.row.col.f32.f16.f16.f32 "
        "{%0,%1,%2,%3}, {%4,%5,%6,%7}, {%8,%9}, {%0,%1,%2,%3};"
        : "+f"(d[0]), "+f"(d[1]), "+f"(d[2]), "+f"(d[3])
        : "r"(a[0]), "r"(a[1]), "r"(a[2]), "r"(a[3]), "r"(b[0]), "r"(b[1]));
}
// fp16 inputs, fp16 accumulator (correction passes; historically 2x rate)
__device__ __forceinline__ void mma_f16(uint32_t* d, const uint32_t* a, const uint32_t* b) {
    asm volatile("mma.sync.aligned.m16n8k16.row.col.f16.f16.f16.f16 "
        "{%0,%1}, {%2,%3,%4,%5}, {%6,%7}, {%0,%1};"
        : "+r"(d[0]), "+r"(d[1])
        : "r"(a[0]), "r"(a[1]), "r"(a[2]), "r"(a[3]), "r"(b[0]), "r"(b[1]));
}
__device__ __forceinline__ __half hf_hi(float x) { return __float2half_rn(x); }
__device__ __forceinline__ __half hf_lo(float x, __half hi) {
    return __float2half_rn(x - __half2float(hi));
}

// ---------------------------------------------------------------------------
// fp16x3 mma GEMM: C[M,N] = (Ah+Al)[M,K] @ (Bh+Bl)[N,K]^T + bias (+res)
// pass1 AhBh -> f32 acc; pass2 AhBl + pass3 AlBh -> f16 acc.
// CTA 128x128, 8 warps (2x4), warp tile 64x32, K-chunk 32.
// 4-stage cp.async pipeline, 160KB smem, one syncthreads per chunk,
// prefetch issued before compute. Pitch 40 fp16 (80B): ldmatrix conflict-free.
// ---------------------------------------------------------------------------
#define GK       32
#define APITCH_B 80
#define COMP_B   10240            // 128 * 80
#define STAGE_B  40960            // Ah, Al, Bh, Bl
#define NSTAGE   4
#define GSMEM    (NSTAGE * STAGE_B)   // 163840

__device__ __forceinline__ void g_load_chunk(
    uint32_t st, int c, int tid,
    const __half* __restrict__ Ah, const __half* __restrict__ Al,
    const __half* __restrict__ Bh, const __half* __restrict__ Bl,
    int K, int m0, int n0)
{
    const int k0 = c * GK;
    #pragma unroll
    for (int i = 0; i < 2; i++) {
        int e = tid + (i << 8);          // 0..511
        int r = e >> 2, cc = e & 3;      // row, 16B chunk in 64B row
        uint32_t so = (uint32_t)(r * APITCH_B + cc * 16);
        size_t goA = (size_t)(m0 + r) * K + k0 + cc * 8;
        size_t goB = (size_t)(n0 + r) * K + k0 + cc * 8;
        cp16(st + so,             Ah + goA);
        cp16(st + COMP_B + so,    Al + goA);
        cp16(st + 2*COMP_B + so,  Bh + goB);
        cp16(st + 3*COMP_B + so,  Bl + goB);
    }
    asm volatile("cp.async.commit_group;" ::: "memory");
}

__global__ void __launch_bounds__(256)
gemm_kernel(const __half* __restrict__ Ah, const __half* __restrict__ Al,
            const __half* __restrict__ Bh, const __half* __restrict__ Bl,
            const float* __restrict__ bias, const float* __restrict__ res,
            float* __restrict__ C, int K, int N)
{
    extern __shared__ __align__(16) char sm_[];
    const uint32_t sb = smem_u32(sm_);
    const int tid  = threadIdx.x;
    const int lane = tid & 31;
    const int wid  = tid >> 5;
    const int wm   = wid >> 2;          // 0..1
    const int wn   = wid & 3;           // 0..3
    const int m0 = blockIdx.y << 7;
    const int n0 = blockIdx.x << 7;
    const int NC = K / GK;

    float    acc[4][4][4];       // f32 main accumulators
    uint32_t acx[4][4][2];       // f16x2 correction accumulators
    #pragma unroll
    for (int i = 0; i < 4; i++)
        #pragma unroll
        for (int j = 0; j < 4; j++) {
            #pragma unroll
            for (int q = 0; q < 4; q++) acc[i][j][q] = 0.f;
            acx[i][j][0] = 0u; acx[i][j][1] = 0u;
        }

    g_load_chunk(sb,               0, tid, Ah, Al, Bh, Bl, K, m0, n0);
    g_load_chunk(sb + STAGE_B,     1, tid, Ah, Al, Bh, Bl, K, m0, n0);
    g_load_chunk(sb + 2 * STAGE_B, 2, tid, Ah, Al, Bh, Bl, K, m0, n0);

    // ldmatrix per-lane source offsets (bytes)
    const int rowA  = (lane & 7) + ((lane >> 3) & 1) * 8;
    const int kaddA = (lane >> 4) * 16;
    const uint32_t a_ld = (uint32_t)((wm * 64 + rowA) * APITCH_B + kaddA);
    const int rowB  = lane & 7;
    const int kaddB = ((lane >> 3) & 1) * 16;
    const uint32_t b_ld = (uint32_t)((wn * 32 + rowB) * APITCH_B + kaddB);

    for (int c = 0; c < NC; c++) {
        asm volatile("cp.async.wait_group 2;" ::: "memory");
        __syncthreads();

        if (c + 3 < NC)
            g_load_chunk(sb + (uint32_t)((c + 3) & 3) * STAGE_B, c + 3, tid,
                         Ah, Al, Bh, Bl, K, m0, n0);

        const uint32_t st = sb + (uint32_t)(c & 3) * STAGE_B;

        #pragma unroll
        for (int kh = 0; kh < 2; kh++) {
            const uint32_t abase = st + a_ld + kh * 32;
            const uint32_t bbase = st + 2*COMP_B + b_ld + kh * 32;

            uint32_t ah[4][4], bh[4][2];
            #pragma unroll
            for (int mt = 0; mt < 4; mt++)
                ldsm_x4(ah[mt], abase + mt * (16 * APITCH_B));
            #pragma unroll
            for (int nt = 0; nt < 4; nt++)
                ldsm_x2(bh[nt], bbase + nt * (8 * APITCH_B));

            // pass 1: Ah x Bh -> f32 acc
            #pragma unroll
            for (int mt = 0; mt < 4; mt++)
                #pragma unroll
                for (int nt = 0; nt < 4; nt++)
                    mma_f32(acc[mt][nt], ah[mt], bh[nt]);

            // pass 2: Ah x Bl -> f16 acc
            uint32_t bl[4][2];
            #pragma unroll
            for (int nt = 0; nt < 4; nt++)
                ldsm_x2(bl[nt], bbase + COMP_B + nt * (8 * APITCH_B));
            #pragma unroll
            for (int mt = 0; mt < 4; mt++)
                #pragma unroll
                for (int nt = 0; nt < 4; nt++)
                    mma_f16(acx[mt][nt], ah[mt], bl[nt]);

            // pass 3: Al x Bh -> f16 acc
            uint32_t al[4][4];
            #pragma unroll
            for (int mt = 0; mt < 4; mt++)
                ldsm_x4(al[mt], abase + COMP_B + mt * (16 * APITCH_B));
            #pragma unroll
            for (int mt = 0; mt < 4; mt++)
                #pragma unroll
                for (int nt = 0; nt < 4; nt++)
                    mma_f16(acx[mt][nt], al[mt], bh[nt]);
        }
    }

    // epilogue: C = acc + corr(f16) + bias (+res)
    #pragma unroll
    for (int mt = 0; mt < 4; mt++) {
        #pragma unroll
        for (int nt = 0; nt < 4; nt++) {
            const int rg = m0 + wm * 64 + mt * 16 + (lane >> 2);
            const int cg = n0 + wn * 32 + nt * 8 + (lane & 3) * 2;
            float2 bv = *(const float2*)(bias + cg);
            float2 x01 = __half22float2(*reinterpret_cast<__half2*>(&acx[mt][nt][0]));
            float2 x23 = __half22float2(*reinterpret_cast<__half2*>(&acx[mt][nt][1]));
            float2 o0, o1;
            o0.x = acc[mt][nt][0] + x01.x + bv.x;
            o0.y = acc[mt][nt][1] + x01.y + bv.y;
            o1.x = acc[mt][nt][2] + x23.x + bv.x;
            o1.y = acc[mt][nt][3] + x23.y + bv.y;
            if (res) {
                float2 r0 = *(const float2*)(res + (size_t)rg * N + cg);
                float2 r1 = *(const float2*)(res + (size_t)(rg + 8) * N + cg);
                o0.x += r0.x; o0.y += r0.y;
                o1.x += r1.x; o1.y += r1.y;
            }
            *(float2*)(C + (size_t)rg * N + cg)       = o0;
            *(float2*)(C + (size_t)(rg + 8) * N + cg) = o1;
        }
    }
}

// ---------------------------------------------------------------------------
// Weight transpose + fp16 split: W[K,N] fp32 -> Th/Tl[N,K] fp16
// ---------------------------------------------------------------------------
__global__ void __launch_bounds__(256)
transp_split(const float* __restrict__ W, __half* __restrict__ Th,
             __half* __restrict__ Tl, int Kd, int Nd)
{
    __shared__ float t[32][33];
    const int n0 = blockIdx.x * 32, k0 = blockIdx.y * 32;
    const int tx = threadIdx.x & 31, ty = threadIdx.x >> 5;
    #pragma unroll
    for (int i = 0; i < 4; i++) {
        int kk = ty + i * 8;
        t[kk][tx] = W[(size_t)(k0 + kk) * Nd + n0 + tx];
    }
    __syncthreads();
    #pragma unroll
    for (int i = 0; i < 4; i++) {
        int nn = ty + i * 8;
        float v = t[tx][nn];
        __half hi = hf_hi(v);
        size_t o = (size_t)(n0 + nn) * Kd + k0 + tx;
        Th[o] = hi;
        Tl[o] = hf_lo(v, hi);
    }
}

// ---------------------------------------------------------------------------
// RMSNorm -> fp16 hi/lo
// ---------------------------------------------------------------------------
__global__ void __launch_bounds__(256)
rmsnorm_split(const float* __restrict__ in, const float* __restrict__ g,
              __half* __restrict__ outh, __half* __restrict__ outl)
{
    __shared__ float red[8];
    const int row = blockIdx.x;
    const int tid = threadIdx.x;
    const float4* inr = (const float4*)(in + (size_t)row * DMODEL);
    float4 v0 = inr[tid];
    float4 v1 = inr[tid + 256];
    float ss = v0.x*v0.x + v0.y*v0.y + v0.z*v0.z + v0.w*v0.w
             + v1.x*v1.x + v1.y*v1.y + v1.z*v1.z + v1.w*v1.w;
    #pragma unroll
    for (int o = 16; o; o >>= 1) ss += __shfl_xor_sync(0xffffffffu, ss, o);
    if ((tid & 31) == 0) red[tid >> 5] = ss;
    __syncthreads();
    float tot = red[0]+red[1]+red[2]+red[3]+red[4]+red[5]+red[6]+red[7];
    float rs = rsqrtf(tot * (1.0f / DMODEL) + 1e-8f);

    const float4* gr = (const float4*)g;
    float4 ga = gr[tid], gb = gr[tid + 256];
    __half2* oh2 = (__half2*)(outh + (size_t)row * DMODEL);
    __half2* ol2 = (__half2*)(outl + (size_t)row * DMODEL);
    float y[8] = { v0.x*rs*ga.x, v0.y*rs*ga.y, v0.z*rs*ga.z, v0.w*rs*ga.w,
                   v1.x*rs*gb.x, v1.y*rs*gb.y, v1.z*rs*gb.z, v1.w*rs*gb.w };
    #pragma unroll
    for (int p = 0; p < 4; p++) {
        __half h0 = hf_hi(y[p*2]), h1 = hf_hi(y[p*2+1]);
        __half2 hh; hh.x = h0; hh.y = h1;
        __half2 ll; ll.x = hf_lo(y[p*2], h0); ll.y = hf_lo(y[p*2+1], h1);
        int base = (p < 2) ? (tid*2 + p) : ((tid+256)*2 + (p-2));
        oh2[base] = hh; ol2[base] = ll;
    }
}

// ---------------------------------------------------------------------------
// RoPE (in place on q,k of qkv)
// ---------------------------------------------------------------------------
__global__ void __launch_bounds__(256)
rope_kernel(float* __restrict__ qkv)
{
    const long idx = (long)blockIdx.x * 256 + threadIdx.x;
    const int  i   = (int)(idx & 63);
    const int  h   = (int)((idx >> 6) & 15);
    const long bl  = idx >> 10;
    const long l   = bl & 2047;

    float freq = expf(-(float)i * 0.14391156642875464f);
    float angle = (float)l * freq;
    float s, c;
    sincosf(angle, &s, &c);

    float* qp = qkv + bl * (3 * DMODEL) + h * HD + i;
    float* kp = qp + DMODEL;
    float q1 = qp[0], q2 = qp[64];
    float k1 = kp[0], k2 = kp[64];
    qp[0]  = q1 * c - q2 * s;
    qp[64] = q2 * c + q1 * s;
    kp[0]  = k1 * c - k2 * s;
    kp[64] = k2 * c + k1 * s;
}

// ---------------------------------------------------------------------------
// Flash attention (causal, fp32), outputs fp16 hi/lo
// ---------------------------------------------------------------------------
#define ATT_BM   64
#define ATT_BN   64
#define QSTRIDE  132
#define PSTRIDE  68
#define ATT_SMEM ((3 * ATT_BM * QSTRIDE + ATT_BM * PSTRIDE) * (int)sizeof(float))

__global__ void __launch_bounds__(256)
attn_kernel(const float* __restrict__ qkv,
            __half* __restrict__ Oh, __half* __restrict__ Ol)
{
    extern __shared__ float smem[];
    float* sQ = smem;
    float* sK = sQ + ATT_BM * QSTRIDE;
    float* sV = sK + ATT_BN * QSTRIDE;
    float* sP = sV + ATT_BN * QSTRIDE;

    const int bh = blockIdx.y;
    const int b  = bh >> 4;
    const int h  = bh & 15;
    const int qi = gridDim.x - 1 - blockIdx.x;
    const int q0 = qi * ATT_BM;
    const int tid = threadIdx.x;
    const int r  = tid >> 2;
    const int qd = tid & 3;

    const float* qbase = qkv + (size_t)(b * LSEQ) * (3 * DMODEL) + h * HD;
    const float* kbase = qbase + DMODEL;
    const float* vbase = qbase + 2 * DMODEL;

    for (int i = tid; i < ATT_BM * 32; i += 256) {
        int row = i >> 5, c4 = (i & 31) << 2;
        *(float4*)(sQ + row * QSTRIDE + c4) =
            *(const float4*)(qbase + (size_t)(q0 + row) * (3 * DMODEL) + c4);
    }

    float accO[32];
    #pragma unroll
    for (int i = 0; i < 32; i++) accO[i] = 0.f;
    float mrow = -1e30f, lrow = 0.f;
    const int qg = q0 + r;
    const float scale = 0.088388347648318447f;

    const int nk = qi + 1;
    for (int kt = 0; kt < nk; kt++) {
        const int k0 = kt * ATT_BN;
        __syncthreads();
        for (int i = tid; i < ATT_BN * 32; i += 256) {
            int row = i >> 5, c4 = (i & 31) << 2;
            size_t goff = (size_t)(k0 + row) * (3 * DMODEL) + c4;
            *(float4*)(sK + row * QSTRIDE + c4) = *(const float4*)(kbase + goff);
            *(float4*)(sV + row * QSTRIDE + c4) = *(const float4*)(vbase + goff);
        }
        __syncthreads();

        float s[16];
        #pragma unroll
        for (int jj = 0; jj < 16; jj++) s[jj] = 0.f;
        const float* qr = sQ + r * QSTRIDE;
        #pragma unroll 2
        for (int d = 0; d < HD; d += 4) {
            float4 qv = *(const float4*)(qr + d);
            #pragma unroll
            for (int jj = 0; jj < 16; jj++) {
                float4 kv = *(const float4*)(sK + (qd + (jj << 2)) * QSTRIDE + d);
                s[jj] = fmaf(qv.x, kv.x, s[jj]);
                s[jj] = fmaf(qv.y, kv.y, s[jj]);
                s[jj] = fmaf(qv.z, kv.z, s[jj]);
                s[jj] = fmaf(qv.w, kv.w, s[jj]);
            }
        }

        float tmax = -1e30f;
        #pragma unroll
        for (int jj = 0; jj < 16; jj++) {
            int jgl = k0 + qd + (jj << 2);
            s[jj] = (jgl <= qg) ? s[jj] * scale : -1e30f;
            tmax = fmaxf(tmax, s[jj]);
        }
        tmax = fmaxf(tmax, __shfl_xor_sync(0xffffffffu, tmax, 1));
        tmax = fmaxf(tmax, __shfl_xor_sync(0xffffffffu, tmax, 2));

        float mnew = fmaxf(mrow, tmax);
        float corr = __expf(mrow - mnew);
        float psum = 0.f;
        #pragma unroll
        for (int jj = 0; jj < 16; jj++) {
            float p = __expf(s[jj] - mnew);
            s[jj] = p;
            psum += p;
        }
        psum += __shfl_xor_sync(0xffffffffu, psum, 1);
        psum += __shfl_xor_sync(0xffffffffu, psum, 2);
        lrow = lrow * corr + psum;
        mrow = mnew;
        #pragma unroll
        for (int i = 0; i < 32; i++) accO[i] *= corr;

        #pragma unroll
        for (int jj = 0; jj < 16; jj++)
            sP[r * PSTRIDE + qd + (jj << 2)] = s[jj];
        __syncthreads();

        const float* prow = sP + r * PSTRIDE;
        #pragma unroll 4
        for (int j = 0; j < ATT_BN; j++) {
            float p = prow[j];
            const float4* vr = (const float4*)(sV + j * QSTRIDE + (qd << 5));
            #pragma unroll
            for (int cc = 0; cc < 8; cc++) {
                float4 vv = vr[cc];
                accO[cc * 4 + 0] = fmaf(p, vv.x, accO[cc * 4 + 0]);
                accO[cc * 4 + 1] = fmaf(p, vv.y, accO[cc * 4 + 1]);
                accO[cc * 4 + 2] = fmaf(p, vv.z, accO[cc * 4 + 2]);
                accO[cc * 4 + 3] = fmaf(p, vv.w, accO[cc * 4 + 3]);
            }
        }
    }

    float inv = 1.f / lrow;
    size_t base = (size_t)(b * LSEQ + qg) * DMODEL + h * HD + (qd << 5);
    __half2* oh2 = (__half2*)(Oh + base);
    __half2* ol2 = (__half2*)(Ol + base);
    #pragma unroll
    for (int cc = 0; cc < 16; cc++) {
        float w0 = accO[cc * 2] * inv;
        float w1 = accO[cc * 2 + 1] * inv;
        __half h0 = hf_hi(w0), h1 = hf_hi(w1);
        __half2 hh; hh.x = h0; hh.y = h1;
        __half2 ll; ll.x = hf_lo(w0, h0); ll.y = hf_lo(w1, h1);
        oh2[cc] = hh; ol2[cc] = ll;
    }
}

// ---------------------------------------------------------------------------
// SwiGLU -> fp16 hi/lo  (per-float4 of the OUTPUT: ROWS*4*DMODEL elements)
// ---------------------------------------------------------------------------
__global__ void __launch_bounds__(256)
swiglu_split(const float* __restrict__ P,
             __half* __restrict__ Fh, __half* __restrict__ Fl)
{
    size_t i4 = (size_t)blockIdx.x * 256 + threadIdx.x;  // output float4 index
    if (i4 >= (size_t)ROWS * 4 * DMODEL / 4) return;
    size_t rr  = i4 >> 11;       // 2048 float4 per 8192-wide output row
    size_t kk4 = i4 & 2047;
    const float4 gt = *(const float4*)(P + rr * 16384 + kk4 * 4);
    const float4 vl = *(const float4*)(P + rr * 16384 + 8192 + kk4 * 4);
    float f[4];
    f[0] = gt.x / (1.f + __expf(-gt.x)) * vl.x;
    f[1] = gt.y / (1.f + __expf(-gt.y)) * vl.y;
    f[2] = gt.z / (1.f + __expf(-gt.z)) * vl.z;
    f[3] = gt.w / (1.f + __expf(-gt.w)) * vl.w;
    size_t ob = rr * 8192 + kk4 * 4;
    __half2* fh2 = (__half2*)(Fh + ob);
    __half2* fl2 = (__half2*)(Fl + ob);
    #pragma unroll
    for (int p = 0; p < 2; p++) {
        __half h0 = hf_hi(f[p*2]), h1 = hf_hi(f[p*2+1]);
        __half2 hh; hh.x = h0; hh.y = h1;
        __half2 ll; ll.x = hf_lo(f[p*2], h0); ll.y = hf_lo(f[p*2+1], h1);
        fh2[p] = hh; fl2[p] = ll;
    }
}

// ---------------------------------------------------------------------------
// Host launcher
// ---------------------------------------------------------------------------
extern "C" void kernel_launch(void* const* d_in, const int* in_sizes, int n_in,
                              void* d_out, int out_size)
{
    const float* x    = (const float*)d_in[0];
    const float* Wqkv = (const float*)d_in[1];
    const float* bqkv = (const float*)d_in[2];
    const float* Wo   = (const float*)d_in[3];
    const float* bo   = (const float*)d_in[4];
    const float* g1   = (const float*)d_in[5];
    const float* g2   = (const float*)d_in[6];
    const float* Wp   = (const float*)d_in[7];
    const float* bp   = (const float*)d_in[8];
    const float* Wff  = (const float*)d_in[9];
    const float* bff  = (const float*)d_in[10];
    float* out = (float*)d_out;

    float *p_qkv, *p_x2, *p_p;
    __half *p_xnh, *p_xnl, *p_oh, *p_ol, *p_ffh, *p_ffl;
    __half *p_wqkvh, *p_wqkvl, *p_woh, *p_wol, *p_wph, *p_wpl, *p_wffh, *p_wffl;
    cudaGetSymbolAddress((void**)&p_qkv, g_qkv);
    cudaGetSymbolAddress((void**)&p_x2,  g_x2);
    cudaGetSymbolAddress((void**)&p_p,   g_p);
    cudaGetSymbolAddress((void**)&p_xnh, g_xnh);  cudaGetSymbolAddress((void**)&p_xnl, g_xnl);
    cudaGetSymbolAddress((void**)&p_oh,  g_oh);   cudaGetSymbolAddress((void**)&p_ol,  g_ol);
    cudaGetSymbolAddress((void**)&p_ffh, g_ffh);  cudaGetSymbolAddress((void**)&p_ffl, g_ffl);
    cudaGetSymbolAddress((void**)&p_wqkvh, g_wqkvh); cudaGetSymbolAddress((void**)&p_wqkvl, g_wqkvl);
    cudaGetSymbolAddress((void**)&p_woh, g_woh);  cudaGetSymbolAddress((void**)&p_wol, g_wol);
    cudaGetSymbolAddress((void**)&p_wph, g_wph);  cudaGetSymbolAddress((void**)&p_wpl, g_wpl);
    cudaGetSymbolAddress((void**)&p_wffh, g_wffh); cudaGetSymbolAddress((void**)&p_wffl, g_wffl);

    cudaFuncSetAttribute(attn_kernel, cudaFuncAttributeMaxDynamicSharedMemorySize, ATT_SMEM);
    cudaFuncSetAttribute(gemm_kernel, cudaFuncAttributeMaxDynamicSharedMemorySize, GSMEM);

    // Weight transposition + fp16 split
    transp_split<<<dim3(3 * DMODEL / 32, DMODEL / 32), 256>>>(Wqkv, p_wqkvh, p_wqkvl, DMODEL, 3 * DMODEL);
    transp_split<<<dim3(DMODEL / 32, DMODEL / 32), 256>>>(Wo, p_woh, p_wol, DMODEL, DMODEL);
    transp_split<<<dim3(8 * DMODEL / 32, DMODEL / 32), 256>>>(Wp, p_wph, p_wpl, DMODEL, 8 * DMODEL);
    transp_split<<<dim3(DMODEL / 32, 4 * DMODEL / 32), 256>>>(Wff, p_wffh, p_wffl, 4 * DMODEL, DMODEL);

    // 1. pre-norm (-> fp16 split)
    rmsnorm_split<<<ROWS, 256>>>(x, g1, p_xnh, p_xnl);

    // 2. QKV projection
    gemm_kernel<<<dim3(3 * DMODEL / 128, ROWS / 128), 256, GSMEM>>>(
        p_xnh, p_xnl, p_wqkvh, p_wqkvl, bqkv, nullptr, p_qkv, DMODEL, 3 * DMODEL);

    // 3. RoPE
    rope_kernel<<<(ROWS * NH * 64) / 256, 256>>>(p_qkv);

    // 4. causal flash attention (-> fp16 split)
    attn_kernel<<<dim3(LSEQ / ATT_BM, BD * NH), 256, ATT_SMEM>>>(p_qkv, p_oh, p_ol);

    // 5. output projection + residual
    gemm_kernel<<<dim3(DMODEL / 128, ROWS / 128), 256, GSMEM>>>(
        p_oh, p_ol, p_woh, p_wol, bo, x, p_x2, DMODEL, DMODEL);

    // 6. second pre-norm (-> fp16 split)
    rmsnorm_split<<<ROWS, 256>>>(p_x2, g2, p_xnh, p_xnl);

    // 7. FFN up-projection
    gemm_kernel<<<dim3(8 * DMODEL / 128, ROWS / 128), 256, GSMEM>>>(
        p_xnh, p_xnl, p_wph, p_wpl, bp, nullptr, p_p, DMODEL, 8 * DMODEL);

    // 8. SwiGLU (-> fp16 split)
    swiglu_split<<<(ROWS * 4 * DMODEL / 4) / 256, 256>>>(p_p, p_ffh, p_ffl);

    // 9. FFN down-projection + residual -> output
    gemm_kernel<<<dim3(DMODEL / 128, ROWS / 128), 256, GSMEM>>>(
        p_ffh, p_ffl, p_wffh, p_wffl, bff, p_x2, out, 4 * DMODEL, DMODEL);
}

// round 9
// speedup vs baseline: 1.7425x; 1.0335x over previous
#include <cuda_runtime.h>
#include <cuda_fp16.h>
#include <math.h>
#include <stdint.h>

// ---------------------------------------------------------------------------
// Problem constants
// ---------------------------------------------------------------------------
#define BD      2
#define LSEQ    2048
#define DMODEL  2048
#define NH      16
#define HD      128
#define ROWS    (BD * LSEQ)      // 4096

// ---------------------------------------------------------------------------
// Scratch (device globals -- no allocation allowed)
// ---------------------------------------------------------------------------
__device__ float g_qkv[ROWS * 3 * DMODEL];                 // 96 MB fp32
__device__ float g_x2 [ROWS * DMODEL];                     // 32 MB fp32
__device__ float g_p  [(size_t)ROWS * 8 * DMODEL];         // 256 MB fp32

__device__ __half g_xnh[ROWS * DMODEL], g_xnl[ROWS * DMODEL];
__device__ __half g_oh [ROWS * DMODEL], g_ol [ROWS * DMODEL];
__device__ __half g_ffh[(size_t)ROWS * 4 * DMODEL], g_ffl[(size_t)ROWS * 4 * DMODEL];
// transposed weights [N, K] fp16 hi/lo
__device__ __half g_wqkvh[3 * DMODEL * DMODEL], g_wqkvl[3 * DMODEL * DMODEL];
__device__ __half g_woh  [DMODEL * DMODEL],     g_wol  [DMODEL * DMODEL];
__device__ __half g_wph  [(size_t)8 * DMODEL * DMODEL], g_wpl[(size_t)8 * DMODEL * DMODEL];
__device__ __half g_wffh [(size_t)4 * DMODEL * DMODEL], g_wffl[(size_t)4 * DMODEL * DMODEL];

// ---------------------------------------------------------------------------
// Helpers
// ---------------------------------------------------------------------------
__device__ __forceinline__ uint32_t smem_u32(const void* p) {
    uint32_t a;
    asm("{ .reg .u64 t; cvta.to.shared.u64 t, %1; cvt.u32.u64 %0, t; }"
        : "=r"(a) : "l"(p));
    return a;
}
__device__ __forceinline__ void cp16(uint32_t dst, const void* src) {
    asm volatile("cp.async.cg.shared.global [%0], [%1], 16;" :: "r"(dst), "l"(src));
}
__device__ __forceinline__ void ldsm_x4(uint32_t* r, uint32_t a) {
    asm volatile("ldmatrix.sync.aligned.m8n8.x4.shared.b16 {%0,%1,%2,%3}, [%4];"
        : "=r"(r[0]), "=r"(r[1]), "=r"(r[2]), "=r"(r[3]) : "r"(a));
}
__device__ __forceinline__ void ldsm_x2(uint32_t* r, uint32_t a) {
    asm volatile("ldmatrix.sync.aligned.m8n8.x2.shared.b16 {%0,%1}, [%2];"
        : "=r"(r[0]), "=r"(r[1]) : "r"(a));
}
__device__ __forceinline__ void mma_f32(float* d, const uint32_t* a, const uint32_t* b) {
    asm volatile("mma.sync.aligned.m16n8k16.row.col.f32.f16.f16.f32 "
        "{%0,%1,%2,%3}, {%4,%5,%6,%7}, {%8,%9}, {%0,%1,%2,%3};"
        : "+f"(d[0]), "+f"(d[1]), "+f"(d[2]), "+f"(d[3])
        : "r"(a[0]), "r"(a[1]), "r"(a[2]), "r"(a[3]), "r"(b[0]), "r"(b[1]));
}
__device__ __forceinline__ __half hf_hi(float x) { return __float2half_rn(x); }
__device__ __forceinline__ __half hf_lo(float x, __half hi) {
    return __float2half_rn(x - __half2float(hi));
}

// ---------------------------------------------------------------------------
// fp16x3 mma GEMM: C[M,N] = (Ah+Al)[M,K] @ (Bh+Bl)[N,K]^T + bias (+res)
// All passes f32 acc. CTA 128x128, 16 warps (4x4), warp tile 32x32.
// 512 threads -> 4 warps/SMSP for latency hiding. K-chunk 32.
// 4-stage cp.async pipeline, 160KB smem, one syncthreads per chunk.
// Pitch 40 fp16 (80B): ldmatrix conflict-free.
// ---------------------------------------------------------------------------
#define GK       32
#define APITCH_B 80
#define COMP_B   10240            // 128 * 80
#define STAGE_B  40960            // Ah, Al, Bh, Bl
#define NSTAGE   4
#define GSMEM    (NSTAGE * STAGE_B)   // 163840

__device__ __forceinline__ void g_load_chunk(
    uint32_t st, int c, int tid,
    const __half* __restrict__ Ah, const __half* __restrict__ Al,
    const __half* __restrict__ Bh, const __half* __restrict__ Bl,
    int K, int m0, int n0)
{
    const int k0 = c * GK;
    // 512 threads, each loads one 16B chunk of each of the 4 arrays
    int r = tid >> 2, cc = tid & 3;      // row 0..127, 16B chunk in 64B row
    uint32_t so = (uint32_t)(r * APITCH_B + cc * 16);
    size_t goA = (size_t)(m0 + r) * K + k0 + cc * 8;
    size_t goB = (size_t)(n0 + r) * K + k0 + cc * 8;
    cp16(st + so,             Ah + goA);
    cp16(st + COMP_B + so,    Al + goA);
    cp16(st + 2*COMP_B + so,  Bh + goB);
    cp16(st + 3*COMP_B + so,  Bl + goB);
    asm volatile("cp.async.commit_group;" ::: "memory");
}

__global__ void __launch_bounds__(512)
gemm_kernel(const __half* __restrict__ Ah, const __half* __restrict__ Al,
            const __half* __restrict__ Bh, const __half* __restrict__ Bl,
            const float* __restrict__ bias, const float* __restrict__ res,
            float* __restrict__ C, int K, int N)
{
    extern __shared__ __align__(16) char sm_[];
    const uint32_t sb = smem_u32(sm_);
    const int tid  = threadIdx.x;
    const int lane = tid & 31;
    const int wid  = tid >> 5;          // 0..15
    const int wm   = wid >> 2;          // 0..3
    const int wn   = wid & 3;           // 0..3
    const int m0 = blockIdx.y << 7;
    const int n0 = blockIdx.x << 7;
    const int NC = K / GK;

    float acc[2][4][4];                 // 32 f32 accumulators
    #pragma unroll
    for (int i = 0; i < 2; i++)
        #pragma unroll
        for (int j = 0; j < 4; j++)
            #pragma unroll
            for (int q = 0; q < 4; q++) acc[i][j][q] = 0.f;

    g_load_chunk(sb,               0, tid, Ah, Al, Bh, Bl, K, m0, n0);
    g_load_chunk(sb + STAGE_B,     1, tid, Ah, Al, Bh, Bl, K, m0, n0);
    g_load_chunk(sb + 2 * STAGE_B, 2, tid, Ah, Al, Bh, Bl, K, m0, n0);

    // ldmatrix per-lane source offsets (bytes)
    const int rowA  = (lane & 7) + ((lane >> 3) & 1) * 8;
    const int kaddA = (lane >> 4) * 16;
    const uint32_t a_ld = (uint32_t)((wm * 32 + rowA) * APITCH_B + kaddA);
    const int rowB  = lane & 7;
    const int kaddB = ((lane >> 3) & 1) * 16;
    const uint32_t b_ld = (uint32_t)((wn * 32 + rowB) * APITCH_B + kaddB);

    for (int c = 0; c < NC; c++) {
        asm volatile("cp.async.wait_group 2;" ::: "memory");
        __syncthreads();

        if (c + 3 < NC)
            g_load_chunk(sb + (uint32_t)((c + 3) & 3) * STAGE_B, c + 3, tid,
                         Ah, Al, Bh, Bl, K, m0, n0);

        const uint32_t st = sb + (uint32_t)(c & 3) * STAGE_B;

        #pragma unroll
        for (int kh = 0; kh < 2; kh++) {
            const uint32_t abase = st + a_ld + kh * 32;
            const uint32_t bbase = st + 2*COMP_B + b_ld + kh * 32;

            uint32_t ah[2][4], bh[4][2];
            #pragma unroll
            for (int mt = 0; mt < 2; mt++)
                ldsm_x4(ah[mt], abase + mt * (16 * APITCH_B));
            #pragma unroll
            for (int nt = 0; nt < 4; nt++)
                ldsm_x2(bh[nt], bbase + nt * (8 * APITCH_B));

            // pass 1: Ah x Bh
            #pragma unroll
            for (int mt = 0; mt < 2; mt++)
                #pragma unroll
                for (int nt = 0; nt < 4; nt++)
                    mma_f32(acc[mt][nt], ah[mt], bh[nt]);

            // pass 2: Ah x Bl
            uint32_t bl[4][2];
            #pragma unroll
            for (int nt = 0; nt < 4; nt++)
                ldsm_x2(bl[nt], bbase + COMP_B + nt * (8 * APITCH_B));
            #pragma unroll
            for (int mt = 0; mt < 2; mt++)
                #pragma unroll
                for (int nt = 0; nt < 4; nt++)
                    mma_f32(acc[mt][nt], ah[mt], bl[nt]);

            // pass 3: Al x Bh
            uint32_t al[2][4];
            #pragma unroll
            for (int mt = 0; mt < 2; mt++)
                ldsm_x4(al[mt], abase + COMP_B + mt * (16 * APITCH_B));
            #pragma unroll
            for (int mt = 0; mt < 2; mt++)
                #pragma unroll
                for (int nt = 0; nt < 4; nt++)
                    mma_f32(acc[mt][nt], al[mt], bh[nt]);
        }
    }

    // epilogue
    #pragma unroll
    for (int mt = 0; mt < 2; mt++) {
        #pragma unroll
        for (int nt = 0; nt < 4; nt++) {
            const int rg = m0 + wm * 32 + mt * 16 + (lane >> 2);
            const int cg = n0 + wn * 32 + nt * 8 + (lane & 3) * 2;
            float2 bv = *(const float2*)(bias + cg);
            float2 o0, o1;
            o0.x = acc[mt][nt][0] + bv.x;  o0.y = acc[mt][nt][1] + bv.y;
            o1.x = acc[mt][nt][2] + bv.x;  o1.y = acc[mt][nt][3] + bv.y;
            if (res) {
                float2 r0 = *(const float2*)(res + (size_t)rg * N + cg);
                float2 r1 = *(const float2*)(res + (size_t)(rg + 8) * N + cg);
                o0.x += r0.x; o0.y += r0.y;
                o1.x += r1.x; o1.y += r1.y;
            }
            *(float2*)(C + (size_t)rg * N + cg)       = o0;
            *(float2*)(C + (size_t)(rg + 8) * N + cg) = o1;
        }
    }
}

// ---------------------------------------------------------------------------
// Weight transpose + fp16 split: W[K,N] fp32 -> Th/Tl[N,K] fp16
// ---------------------------------------------------------------------------
__global__ void __launch_bounds__(256)
transp_split(const float* __restrict__ W, __half* __restrict__ Th,
             __half* __restrict__ Tl, int Kd, int Nd)
{
    __shared__ float t[32][33];
    const int n0 = blockIdx.x * 32, k0 = blockIdx.y * 32;
    const int tx = threadIdx.x & 31, ty = threadIdx.x >> 5;
    #pragma unroll
    for (int i = 0; i < 4; i++) {
        int kk = ty + i * 8;
        t[kk][tx] = W[(size_t)(k0 + kk) * Nd + n0 + tx];
    }
    __syncthreads();
    #pragma unroll
    for (int i = 0; i < 4; i++) {
        int nn = ty + i * 8;
        float v = t[tx][nn];
        __half hi = hf_hi(v);
        size_t o = (size_t)(n0 + nn) * Kd + k0 + tx;
        Th[o] = hi;
        Tl[o] = hf_lo(v, hi);
    }
}

// ---------------------------------------------------------------------------
// RMSNorm -> fp16 hi/lo
// ---------------------------------------------------------------------------
__global__ void __launch_bounds__(256)
rmsnorm_split(const float* __restrict__ in, const float* __restrict__ g,
              __half* __restrict__ outh, __half* __restrict__ outl)
{
    __shared__ float red[8];
    const int row = blockIdx.x;
    const int tid = threadIdx.x;
    const float4* inr = (const float4*)(in + (size_t)row * DMODEL);
    float4 v0 = inr[tid];
    float4 v1 = inr[tid + 256];
    float ss = v0.x*v0.x + v0.y*v0.y + v0.z*v0.z + v0.w*v0.w
             + v1.x*v1.x + v1.y*v1.y + v1.z*v1.z + v1.w*v1.w;
    #pragma unroll
    for (int o = 16; o; o >>= 1) ss += __shfl_xor_sync(0xffffffffu, ss, o);
    if ((tid & 31) == 0) red[tid >> 5] = ss;
    __syncthreads();
    float tot = red[0]+red[1]+red[2]+red[3]+red[4]+red[5]+red[6]+red[7];
    float rs = rsqrtf(tot * (1.0f / DMODEL) + 1e-8f);

    const float4* gr = (const float4*)g;
    float4 ga = gr[tid], gb = gr[tid + 256];
    __half2* oh2 = (__half2*)(outh + (size_t)row * DMODEL);
    __half2* ol2 = (__half2*)(outl + (size_t)row * DMODEL);
    float y[8] = { v0.x*rs*ga.x, v0.y*rs*ga.y, v0.z*rs*ga.z, v0.w*rs*ga.w,
                   v1.x*rs*gb.x, v1.y*rs*gb.y, v1.z*rs*gb.z, v1.w*rs*gb.w };
    #pragma unroll
    for (int p = 0; p < 4; p++) {
        __half h0 = hf_hi(y[p*2]), h1 = hf_hi(y[p*2+1]);
        __half2 hh; hh.x = h0; hh.y = h1;
        __half2 ll; ll.x = hf_lo(y[p*2], h0); ll.y = hf_lo(y[p*2+1], h1);
        int base = (p < 2) ? (tid*2 + p) : ((tid+256)*2 + (p-2));
        oh2[base] = hh; ol2[base] = ll;
    }
}

// ---------------------------------------------------------------------------
// RoPE (in place on q,k of qkv)
// ---------------------------------------------------------------------------
__global__ void __launch_bounds__(256)
rope_kernel(float* __restrict__ qkv)
{
    const long idx = (long)blockIdx.x * 256 + threadIdx.x;
    const int  i   = (int)(idx & 63);
    const int  h   = (int)((idx >> 6) & 15);
    const long bl  = idx >> 10;
    const long l   = bl & 2047;

    float freq = expf(-(float)i * 0.14391156642875464f);
    float angle = (float)l * freq;
    float s, c;
    sincosf(angle, &s, &c);

    float* qp = qkv + bl * (3 * DMODEL) + h * HD + i;
    float* kp = qp + DMODEL;
    float q1 = qp[0], q2 = qp[64];
    float k1 = kp[0], k2 = kp[64];
    qp[0]  = q1 * c - q2 * s;
    qp[64] = q2 * c + q1 * s;
    kp[0]  = k1 * c - k2 * s;
    kp[64] = k2 * c + k1 * s;
}

// ---------------------------------------------------------------------------
// Flash attention (causal, fp32), outputs fp16 hi/lo
// ---------------------------------------------------------------------------
#define ATT_BM   64
#define ATT_BN   64
#define QSTRIDE  132
#define PSTRIDE  68
#define ATT_SMEM ((3 * ATT_BM * QSTRIDE + ATT_BM * PSTRIDE) * (int)sizeof(float))

__global__ void __launch_bounds__(256)
attn_kernel(const float* __restrict__ qkv,
            __half* __restrict__ Oh, __half* __restrict__ Ol)
{
    extern __shared__ float smem[];
    float* sQ = smem;
    float* sK = sQ + ATT_BM * QSTRIDE;
    float* sV = sK + ATT_BN * QSTRIDE;
    float* sP = sV + ATT_BN * QSTRIDE;

    const int bh = blockIdx.y;
    const int b  = bh >> 4;
    const int h  = bh & 15;
    const int qi = gridDim.x - 1 - blockIdx.x;
    const int q0 = qi * ATT_BM;
    const int tid = threadIdx.x;
    const int r  = tid >> 2;
    const int qd = tid & 3;

    const float* qbase = qkv + (size_t)(b * LSEQ) * (3 * DMODEL) + h * HD;
    const float* kbase = qbase + DMODEL;
    const float* vbase = qbase + 2 * DMODEL;

    for (int i = tid; i < ATT_BM * 32; i += 256) {
        int row = i >> 5, c4 = (i & 31) << 2;
        *(float4*)(sQ + row * QSTRIDE + c4) =
            *(const float4*)(qbase + (size_t)(q0 + row) * (3 * DMODEL) + c4);
    }

    float accO[32];
    #pragma unroll
    for (int i = 0; i < 32; i++) accO[i] = 0.f;
    float mrow = -1e30f, lrow = 0.f;
    const int qg = q0 + r;
    const float scale = 0.088388347648318447f;

    const int nk = qi + 1;
    for (int kt = 0; kt < nk; kt++) {
        const int k0 = kt * ATT_BN;
        __syncthreads();
        for (int i = tid; i < ATT_BN * 32; i += 256) {
            int row = i >> 5, c4 = (i & 31) << 2;
            size_t goff = (size_t)(k0 + row) * (3 * DMODEL) + c4;
            *(float4*)(sK + row * QSTRIDE + c4) = *(const float4*)(kbase + goff);
            *(float4*)(sV + row * QSTRIDE + c4) = *(const float4*)(vbase + goff);
        }
        __syncthreads();

        float s[16];
        #pragma unroll
        for (int jj = 0; jj < 16; jj++) s[jj] = 0.f;
        const float* qr = sQ + r * QSTRIDE;
        #pragma unroll 2
        for (int d = 0; d < HD; d += 4) {
            float4 qv = *(const float4*)(qr + d);
            #pragma unroll
            for (int jj = 0; jj < 16; jj++) {
                float4 kv = *(const float4*)(sK + (qd + (jj << 2)) * QSTRIDE + d);
                s[jj] = fmaf(qv.x, kv.x, s[jj]);
                s[jj] = fmaf(qv.y, kv.y, s[jj]);
                s[jj] = fmaf(qv.z, kv.z, s[jj]);
                s[jj] = fmaf(qv.w, kv.w, s[jj]);
            }
        }

        float tmax = -1e30f;
        #pragma unroll
        for (int jj = 0; jj < 16; jj++) {
            int jgl = k0 + qd + (jj << 2);
            s[jj] = (jgl <= qg) ? s[jj] * scale : -1e30f;
            tmax = fmaxf(tmax, s[jj]);
        }
        tmax = fmaxf(tmax, __shfl_xor_sync(0xffffffffu, tmax, 1));
        tmax = fmaxf(tmax, __shfl_xor_sync(0xffffffffu, tmax, 2));

        float mnew = fmaxf(mrow, tmax);
        float corr = __expf(mrow - mnew);
        float psum = 0.f;
        #pragma unroll
        for (int jj = 0; jj < 16; jj++) {
            float p = __expf(s[jj] - mnew);
            s[jj] = p;
            psum += p;
        }
        psum += __shfl_xor_sync(0xffffffffu, psum, 1);
        psum += __shfl_xor_sync(0xffffffffu, psum, 2);
        lrow = lrow * corr + psum;
        mrow = mnew;
        #pragma unroll
        for (int i = 0; i < 32; i++) accO[i] *= corr;

        #pragma unroll
        for (int jj = 0; jj < 16; jj++)
            sP[r * PSTRIDE + qd + (jj << 2)] = s[jj];
        __syncthreads();

        const float* prow = sP + r * PSTRIDE;
        #pragma unroll 4
        for (int j = 0; j < ATT_BN; j++) {
            float p = prow[j];
            const float4* vr = (const float4*)(sV + j * QSTRIDE + (qd << 5));
            #pragma unroll
            for (int cc = 0; cc < 8; cc++) {
                float4 vv = vr[cc];
                accO[cc * 4 + 0] = fmaf(p, vv.x, accO[cc * 4 + 0]);
                accO[cc * 4 + 1] = fmaf(p, vv.y, accO[cc * 4 + 1]);
                accO[cc * 4 + 2] = fmaf(p, vv.z, accO[cc * 4 + 2]);
                accO[cc * 4 + 3] = fmaf(p, vv.w, accO[cc * 4 + 3]);
            }
        }
    }

    float inv = 1.f / lrow;
    size_t base = (size_t)(b * LSEQ + qg) * DMODEL + h * HD + (qd << 5);
    __half2* oh2 = (__half2*)(Oh + base);
    __half2* ol2 = (__half2*)(Ol + base);
    #pragma unroll
    for (int cc = 0; cc < 16; cc++) {
        float w0 = accO[cc * 2] * inv;
        float w1 = accO[cc * 2 + 1] * inv;
        __half h0 = hf_hi(w0), h1 = hf_hi(w1);
        __half2 hh; hh.x = h0; hh.y = h1;
        __half2 ll; ll.x = hf_lo(w0, h0); ll.y = hf_lo(w1, h1);
        oh2[cc] = hh; ol2[cc] = ll;
    }
}

// ---------------------------------------------------------------------------
// SwiGLU -> fp16 hi/lo  (per-float4 of the OUTPUT: ROWS*4*DMODEL elements)
// ---------------------------------------------------------------------------
__global__ void __launch_bounds__(256)
swiglu_split(const float* __restrict__ P,
             __half* __restrict__ Fh, __half* __restrict__ Fl)
{
    size_t i4 = (size_t)blockIdx.x * 256 + threadIdx.x;  // output float4 index
    if (i4 >= (size_t)ROWS * 4 * DMODEL / 4) return;
    size_t rr  = i4 >> 11;       // 2048 float4 per 8192-wide output row
    size_t kk4 = i4 & 2047;
    const float4 gt = *(const float4*)(P + rr * 16384 + kk4 * 4);
    const float4 vl = *(const float4*)(P + rr * 16384 + 8192 + kk4 * 4);
    float f[4];
    f[0] = gt.x / (1.f + __expf(-gt.x)) * vl.x;
    f[1] = gt.y / (1.f + __expf(-gt.y)) * vl.y;
    f[2] = gt.z / (1.f + __expf(-gt.z)) * vl.z;
    f[3] = gt.w / (1.f + __expf(-gt.w)) * vl.w;
    size_t ob = rr * 8192 + kk4 * 4;
    __half2* fh2 = (__half2*)(Fh + ob);
    __half2* fl2 = (__half2*)(Fl + ob);
    #pragma unroll
    for (int p = 0; p < 2; p++) {
        __half h0 = hf_hi(f[p*2]), h1 = hf_hi(f[p*2+1]);
        __half2 hh; hh.x = h0; hh.y = h1;
        __half2 ll; ll.x = hf_lo(f[p*2], h0); ll.y = hf_lo(f[p*2+1], h1);
        fh2[p] = hh; fl2[p] = ll;
    }
}

// ---------------------------------------------------------------------------
// Host launcher
// ---------------------------------------------------------------------------
extern "C" void kernel_launch(void* const* d_in, const int* in_sizes, int n_in,
                              void* d_out, int out_size)
{
    const float* x    = (const float*)d_in[0];
    const float* Wqkv = (const float*)d_in[1];
    const float* bqkv = (const float*)d_in[2];
    const float* Wo   = (const float*)d_in[3];
    const float* bo   = (const float*)d_in[4];
    const float* g1   = (const float*)d_in[5];
    const float* g2   = (const float*)d_in[6];
    const float* Wp   = (const float*)d_in[7];
    const float* bp   = (const float*)d_in[8];
    const float* Wff  = (const float*)d_in[9];
    const float* bff  = (const float*)d_in[10];
    float* out = (float*)d_out;

    float *p_qkv, *p_x2, *p_p;
    __half *p_xnh, *p_xnl, *p_oh, *p_ol, *p_ffh, *p_ffl;
    __half *p_wqkvh, *p_wqkvl, *p_woh, *p_wol, *p_wph, *p_wpl, *p_wffh, *p_wffl;
    cudaGetSymbolAddress((void**)&p_qkv, g_qkv);
    cudaGetSymbolAddress((void**)&p_x2,  g_x2);
    cudaGetSymbolAddress((void**)&p_p,   g_p);
    cudaGetSymbolAddress((void**)&p_xnh, g_xnh);  cudaGetSymbolAddress((void**)&p_xnl, g_xnl);
    cudaGetSymbolAddress((void**)&p_oh,  g_oh);   cudaGetSymbolAddress((void**)&p_ol,  g_ol);
    cudaGetSymbolAddress((void**)&p_ffh, g_ffh);  cudaGetSymbolAddress((void**)&p_ffl, g_ffl);
    cudaGetSymbolAddress((void**)&p_wqkvh, g_wqkvh); cudaGetSymbolAddress((void**)&p_wqkvl, g_wqkvl);
    cudaGetSymbolAddress((void**)&p_woh, g_woh);  cudaGetSymbolAddress((void**)&p_wol, g_wol);
    cudaGetSymbolAddress((void**)&p_wph, g_wph);  cudaGetSymbolAddress((void**)&p_wpl, g_wpl);
    cudaGetSymbolAddress((void**)&p_wffh, g_wffh); cudaGetSymbolAddress((void**)&p_wffl, g_wffl);

    cudaFuncSetAttribute(attn_kernel, cudaFuncAttributeMaxDynamicSharedMemorySize, ATT_SMEM);
    cudaFuncSetAttribute(gemm_kernel, cudaFuncAttributeMaxDynamicSharedMemorySize, GSMEM);

    // Weight transposition + fp16 split
    transp_split<<<dim3(3 * DMODEL / 32, DMODEL / 32), 256>>>(Wqkv, p_wqkvh, p_wqkvl, DMODEL, 3 * DMODEL);
    transp_split<<<dim3(DMODEL / 32, DMODEL / 32), 256>>>(Wo, p_woh, p_wol, DMODEL, DMODEL);
    transp_split<<<dim3(8 * DMODEL / 32, DMODEL / 32), 256>>>(Wp, p_wph, p_wpl, DMODEL, 8 * DMODEL);
    transp_split<<<dim3(DMODEL / 32, 4 * DMODEL / 32), 256>>>(Wff, p_wffh, p_wffl, 4 * DMODEL, DMODEL);

    // 1. pre-norm (-> fp16 split)
    rmsnorm_split<<<ROWS, 256>>>(x, g1, p_xnh, p_xnl);

    // 2. QKV projection
    gemm_kernel<<<dim3(3 * DMODEL / 128, ROWS / 128), 512, GSMEM>>>(
        p_xnh, p_xnl, p_wqkvh, p_wqkvl, bqkv, nullptr, p_qkv, DMODEL, 3 * DMODEL);

    // 3. RoPE
    rope_kernel<<<(ROWS * NH * 64) / 256, 256>>>(p_qkv);

    // 4. causal flash attention (-> fp16 split)
    attn_kernel<<<dim3(LSEQ / ATT_BM, BD * NH), 256, ATT_SMEM>>>(p_qkv, p_oh, p_ol);

    // 5. output projection + residual
    gemm_kernel<<<dim3(DMODEL / 128, ROWS / 128), 512, GSMEM>>>(
        p_oh, p_ol, p_woh, p_wol, bo, x, p_x2, DMODEL, DMODEL);

    // 6. second pre-norm (-> fp16 split)
    rmsnorm_split<<<ROWS, 256>>>(p_x2, g2, p_xnh, p_xnl);

    // 7. FFN up-projection
    gemm_kernel<<<dim3(8 * DMODEL / 128, ROWS / 128), 512, GSMEM>>>(
        p_xnh, p_xnl, p_wph, p_wpl, bp, nullptr, p_p, DMODEL, 8 * DMODEL);

    // 8. SwiGLU (-> fp16 split)
    swiglu_split<<<(ROWS * 4 * DMODEL / 4) / 256, 256>>>(p_p, p_ffh, p_ffl);

    // 9. FFN down-projection + residual -> output
    gemm_kernel<<<dim3(DMODEL / 128, ROWS / 128), 512, GSMEM>>>(
        p_ffh, p_ffl, p_wffh, p_wffl, bff, p_x2, out, 4 * DMODEL, DMODEL);
}

// round 10
// speedup vs baseline: 2.0095x; 1.1533x over previous
#include <cuda_runtime.h>
#include <cuda_fp16.h>
#include <math.h>
#include <stdint.h>

// ---------------------------------------------------------------------------
// Problem constants
// ---------------------------------------------------------------------------
#define BD      2
#define LSEQ    2048
#define DMODEL  2048
#define NH      16
#define HD      128
#define ROWS    (BD * LSEQ)      // 4096

// ---------------------------------------------------------------------------
// Scratch (device globals -- no allocation allowed)
// ---------------------------------------------------------------------------
__device__ float g_qkv[ROWS * 3 * DMODEL];                 // 96 MB fp32
__device__ float g_x2 [ROWS * DMODEL];                     // 32 MB fp32
__device__ float g_p  [(size_t)ROWS * 8 * DMODEL];         // 256 MB fp32

__device__ __half g_xnh[ROWS * DMODEL], g_xnl[ROWS * DMODEL];
__device__ __half g_oh [ROWS * DMODEL], g_ol [ROWS * DMODEL];
__device__ __half g_ffh[(size_t)ROWS * 4 * DMODEL], g_ffl[(size_t)ROWS * 4 * DMODEL];
// transposed weights [N, K] fp16 (hi digit only)
__device__ __half g_wqkvh[3 * DMODEL * DMODEL];
__device__ __half g_woh  [DMODEL * DMODEL];
__device__ __half g_wph  [(size_t)8 * DMODEL * DMODEL];
__device__ __half g_wffh [(size_t)4 * DMODEL * DMODEL];

// ---------------------------------------------------------------------------
// Helpers
// ---------------------------------------------------------------------------
__device__ __forceinline__ uint32_t smem_u32(const void* p) {
    uint32_t a;
    asm("{ .reg .u64 t; cvta.to.shared.u64 t, %1; cvt.u32.u64 %0, t; }"
        : "=r"(a) : "l"(p));
    return a;
}
__device__ __forceinline__ void cp16(uint32_t dst, const void* src) {
    asm volatile("cp.async.cg.shared.global [%0], [%1], 16;" :: "r"(dst), "l"(src));
}
__device__ __forceinline__ void ldsm_x4(uint32_t* r, uint32_t a) {
    asm volatile("ldmatrix.sync.aligned.m8n8.x4.shared.b16 {%0,%1,%2,%3}, [%4];"
        : "=r"(r[0]), "=r"(r[1]), "=r"(r[2]), "=r"(r[3]) : "r"(a));
}
__device__ __forceinline__ void ldsm_x2(uint32_t* r, uint32_t a) {
    asm volatile("ldmatrix.sync.aligned.m8n8.x2.shared.b16 {%0,%1}, [%2];"
        : "=r"(r[0]), "=r"(r[1]) : "r"(a));
}
__device__ __forceinline__ void mma_f32(float* d, const uint32_t* a, const uint32_t* b) {
    asm volatile("mma.sync.aligned.m16n8k16.row.col.f32.f16.f16.f32 "
        "{%0,%1,%2,%3}, {%4,%5,%6,%7}, {%8,%9}, {%0,%1,%2,%3};"
        : "+f"(d[0]), "+f"(d[1]), "+f"(d[2]), "+f"(d[3])
        : "r"(a[0]), "r"(a[1]), "r"(a[2]), "r"(a[3]), "r"(b[0]), "r"(b[1]));
}
__device__ __forceinline__ __half hf_hi(float x) { return __float2half_rn(x); }
__device__ __forceinline__ __half hf_lo(float x, __half hi) {
    return __float2half_rn(x - __half2float(hi));
}

// ---------------------------------------------------------------------------
// fp16x2 mma GEMM: C[M,N] = (Ah+Al)[M,K] @ Bh[N,K]^T + bias (+res)
// (weight-lo digit dropped; error ~ 2^-12 weight quantization, quadrature-
//  summed over K -> ~2.3e-4 per GEMM output, fp32 acc everywhere)
// CTA 128x128, 16 warps (4x4), warp tile 32x32, 512 threads (4 warps/SMSP).
// K-chunk 32, 4-stage cp.async pipeline (120KB smem), one sync per chunk.
// Pitch 40 fp16 (80B): ldmatrix conflict-free.
// ---------------------------------------------------------------------------
#define GK       32
#define APITCH_B 80
#define COMP_B   10240            // 128 * 80
#define STAGE_B  30720            // Ah, Al, Bh
#define NSTAGE   4
#define GSMEM    (NSTAGE * STAGE_B)   // 122880

__device__ __forceinline__ void g_load_chunk(
    uint32_t st, int c, int tid,
    const __half* __restrict__ Ah, const __half* __restrict__ Al,
    const __half* __restrict__ Bh,
    int K, int m0, int n0)
{
    const int k0 = c * GK;
    // 512 threads: each loads one 16B chunk of each of the 3 arrays
    int r = tid >> 2, cc = tid & 3;      // row 0..127, 16B chunk in 64B row
    uint32_t so = (uint32_t)(r * APITCH_B + cc * 16);
    size_t goA = (size_t)(m0 + r) * K + k0 + cc * 8;
    size_t goB = (size_t)(n0 + r) * K + k0 + cc * 8;
    cp16(st + so,             Ah + goA);
    cp16(st + COMP_B + so,    Al + goA);
    cp16(st + 2*COMP_B + so,  Bh + goB);
    asm volatile("cp.async.commit_group;" ::: "memory");
}

__global__ void __launch_bounds__(512)
gemm_kernel(const __half* __restrict__ Ah, const __half* __restrict__ Al,
            const __half* __restrict__ Bh,
            const float* __restrict__ bias, const float* __restrict__ res,
            float* __restrict__ C, int K, int N)
{
    extern __shared__ __align__(16) char sm_[];
    const uint32_t sb = smem_u32(sm_);
    const int tid  = threadIdx.x;
    const int lane = tid & 31;
    const int wid  = tid >> 5;          // 0..15
    const int wm   = wid >> 2;          // 0..3
    const int wn   = wid & 3;           // 0..3
    const int m0 = blockIdx.y << 7;
    const int n0 = blockIdx.x << 7;
    const int NC = K / GK;

    float acc[2][4][4];
    #pragma unroll
    for (int i = 0; i < 2; i++)
        #pragma unroll
        for (int j = 0; j < 4; j++)
            #pragma unroll
            for (int q = 0; q < 4; q++) acc[i][j][q] = 0.f;

    g_load_chunk(sb,               0, tid, Ah, Al, Bh, K, m0, n0);
    g_load_chunk(sb + STAGE_B,     1, tid, Ah, Al, Bh, K, m0, n0);
    g_load_chunk(sb + 2 * STAGE_B, 2, tid, Ah, Al, Bh, K, m0, n0);

    // ldmatrix per-lane source offsets (bytes)
    const int rowA  = (lane & 7) + ((lane >> 3) & 1) * 8;
    const int kaddA = (lane >> 4) * 16;
    const uint32_t a_ld = (uint32_t)((wm * 32 + rowA) * APITCH_B + kaddA);
    const int rowB  = lane & 7;
    const int kaddB = ((lane >> 3) & 1) * 16;
    const uint32_t b_ld = (uint32_t)((wn * 32 + rowB) * APITCH_B + kaddB);

    for (int c = 0; c < NC; c++) {
        asm volatile("cp.async.wait_group 2;" ::: "memory");
        __syncthreads();

        if (c + 3 < NC)
            g_load_chunk(sb + (uint32_t)((c + 3) & 3) * STAGE_B, c + 3, tid,
                         Ah, Al, Bh, K, m0, n0);

        const uint32_t st = sb + (uint32_t)(c & 3) * STAGE_B;

        #pragma unroll
        for (int kh = 0; kh < 2; kh++) {
            const uint32_t abase = st + a_ld + kh * 32;
            const uint32_t bbase = st + 2*COMP_B + b_ld + kh * 32;

            uint32_t ah[2][4], bh[4][2];
            #pragma unroll
            for (int mt = 0; mt < 2; mt++)
                ldsm_x4(ah[mt], abase + mt * (16 * APITCH_B));
            #pragma unroll
            for (int nt = 0; nt < 4; nt++)
                ldsm_x2(bh[nt], bbase + nt * (8 * APITCH_B));

            // pass 1: Ah x Bh
            #pragma unroll
            for (int mt = 0; mt < 2; mt++)
                #pragma unroll
                for (int nt = 0; nt < 4; nt++)
                    mma_f32(acc[mt][nt], ah[mt], bh[nt]);

            // pass 2: Al x Bh
            uint32_t al[2][4];
            #pragma unroll
            for (int mt = 0; mt < 2; mt++)
                ldsm_x4(al[mt], abase + COMP_B + mt * (16 * APITCH_B));
            #pragma unroll
            for (int mt = 0; mt < 2; mt++)
                #pragma unroll
                for (int nt = 0; nt < 4; nt++)
                    mma_f32(acc[mt][nt], al[mt], bh[nt]);
        }
    }

    // epilogue
    #pragma unroll
    for (int mt = 0; mt < 2; mt++) {
        #pragma unroll
        for (int nt = 0; nt < 4; nt++) {
            const int rg = m0 + wm * 32 + mt * 16 + (lane >> 2);
            const int cg = n0 + wn * 32 + nt * 8 + (lane & 3) * 2;
            float2 bv = *(const float2*)(bias + cg);
            float2 o0, o1;
            o0.x = acc[mt][nt][0] + bv.x;  o0.y = acc[mt][nt][1] + bv.y;
            o1.x = acc[mt][nt][2] + bv.x;  o1.y = acc[mt][nt][3] + bv.y;
            if (res) {
                float2 r0 = *(const float2*)(res + (size_t)rg * N + cg);
                float2 r1 = *(const float2*)(res + (size_t)(rg + 8) * N + cg);
                o0.x += r0.x; o0.y += r0.y;
                o1.x += r1.x; o1.y += r1.y;
            }
            *(float2*)(C + (size_t)rg * N + cg)       = o0;
            *(float2*)(C + (size_t)(rg + 8) * N + cg) = o1;
        }
    }
}

// ---------------------------------------------------------------------------
// Weight transpose + fp16 round: W[K,N] fp32 -> Th[N,K] fp16
// ---------------------------------------------------------------------------
__global__ void __launch_bounds__(256)
transp_half(const float* __restrict__ W, __half* __restrict__ Th, int Kd, int Nd)
{
    __shared__ float t[32][33];
    const int n0 = blockIdx.x * 32, k0 = blockIdx.y * 32;
    const int tx = threadIdx.x & 31, ty = threadIdx.x >> 5;
    #pragma unroll
    for (int i = 0; i < 4; i++) {
        int kk = ty + i * 8;
        t[kk][tx] = W[(size_t)(k0 + kk) * Nd + n0 + tx];
    }
    __syncthreads();
    #pragma unroll
    for (int i = 0; i < 4; i++) {
        int nn = ty + i * 8;
        Th[(size_t)(n0 + nn) * Kd + k0 + tx] = hf_hi(t[tx][nn]);
    }
}

// ---------------------------------------------------------------------------
// RMSNorm -> fp16 hi/lo
// ---------------------------------------------------------------------------
__global__ void __launch_bounds__(256)
rmsnorm_split(const float* __restrict__ in, const float* __restrict__ g,
              __half* __restrict__ outh, __half* __restrict__ outl)
{
    __shared__ float red[8];
    const int row = blockIdx.x;
    const int tid = threadIdx.x;
    const float4* inr = (const float4*)(in + (size_t)row * DMODEL);
    float4 v0 = inr[tid];
    float4 v1 = inr[tid + 256];
    float ss = v0.x*v0.x + v0.y*v0.y + v0.z*v0.z + v0.w*v0.w
             + v1.x*v1.x + v1.y*v1.y + v1.z*v1.z + v1.w*v1.w;
    #pragma unroll
    for (int o = 16; o; o >>= 1) ss += __shfl_xor_sync(0xffffffffu, ss, o);
    if ((tid & 31) == 0) red[tid >> 5] = ss;
    __syncthreads();
    float tot = red[0]+red[1]+red[2]+red[3]+red[4]+red[5]+red[6]+red[7];
    float rs = rsqrtf(tot * (1.0f / DMODEL) + 1e-8f);

    const float4* gr = (const float4*)g;
    float4 ga = gr[tid], gb = gr[tid + 256];
    __half2* oh2 = (__half2*)(outh + (size_t)row * DMODEL);
    __half2* ol2 = (__half2*)(outl + (size_t)row * DMODEL);
    float y[8] = { v0.x*rs*ga.x, v0.y*rs*ga.y, v0.z*rs*ga.z, v0.w*rs*ga.w,
                   v1.x*rs*gb.x, v1.y*rs*gb.y, v1.z*rs*gb.z, v1.w*rs*gb.w };
    #pragma unroll
    for (int p = 0; p < 4; p++) {
        __half h0 = hf_hi(y[p*2]), h1 = hf_hi(y[p*2+1]);
        __half2 hh; hh.x = h0; hh.y = h1;
        __half2 ll; ll.x = hf_lo(y[p*2], h0); ll.y = hf_lo(y[p*2+1], h1);
        int base = (p < 2) ? (tid*2 + p) : ((tid+256)*2 + (p-2));
        oh2[base] = hh; ol2[base] = ll;
    }
}

// ---------------------------------------------------------------------------
// RoPE (in place on q,k of qkv)
// ---------------------------------------------------------------------------
__global__ void __launch_bounds__(256)
rope_kernel(float* __restrict__ qkv)
{
    const long idx = (long)blockIdx.x * 256 + threadIdx.x;
    const int  i   = (int)(idx & 63);
    const int  h   = (int)((idx >> 6) & 15);
    const long bl  = idx >> 10;
    const long l   = bl & 2047;

    float freq = expf(-(float)i * 0.14391156642875464f);
    float angle = (float)l * freq;
    float s, c;
    sincosf(angle, &s, &c);

    float* qp = qkv + bl * (3 * DMODEL) + h * HD + i;
    float* kp = qp + DMODEL;
    float q1 = qp[0], q2 = qp[64];
    float k1 = kp[0], k2 = kp[64];
    qp[0]  = q1 * c - q2 * s;
    qp[64] = q2 * c + q1 * s;
    kp[0]  = k1 * c - k2 * s;
    kp[64] = k2 * c + k1 * s;
}

// ---------------------------------------------------------------------------
// Flash attention (causal, fp32), outputs fp16 hi/lo
// ---------------------------------------------------------------------------
#define ATT_BM   64
#define ATT_BN   64
#define QSTRIDE  132
#define PSTRIDE  68
#define ATT_SMEM ((3 * ATT_BM * QSTRIDE + ATT_BM * PSTRIDE) * (int)sizeof(float))

__global__ void __launch_bounds__(256)
attn_kernel(const float* __restrict__ qkv,
            __half* __restrict__ Oh, __half* __restrict__ Ol)
{
    extern __shared__ float smem[];
    float* sQ = smem;
    float* sK = sQ + ATT_BM * QSTRIDE;
    float* sV = sK + ATT_BN * QSTRIDE;
    float* sP = sV + ATT_BN * QSTRIDE;

    const int bh = blockIdx.y;
    const int b  = bh >> 4;
    const int h  = bh & 15;
    const int qi = gridDim.x - 1 - blockIdx.x;
    const int q0 = qi * ATT_BM;
    const int tid = threadIdx.x;
    const int r  = tid >> 2;
    const int qd = tid & 3;

    const float* qbase = qkv + (size_t)(b * LSEQ) * (3 * DMODEL) + h * HD;
    const float* kbase = qbase + DMODEL;
    const float* vbase = qbase + 2 * DMODEL;

    for (int i = tid; i < ATT_BM * 32; i += 256) {
        int row = i >> 5, c4 = (i & 31) << 2;
        *(float4*)(sQ + row * QSTRIDE + c4) =
            *(const float4*)(qbase + (size_t)(q0 + row) * (3 * DMODEL) + c4);
    }

    float accO[32];
    #pragma unroll
    for (int i = 0; i < 32; i++) accO[i] = 0.f;
    float mrow = -1e30f, lrow = 0.f;
    const int qg = q0 + r;
    const float scale = 0.088388347648318447f;

    const int nk = qi + 1;
    for (int kt = 0; kt < nk; kt++) {
        const int k0 = kt * ATT_BN;
        __syncthreads();
        for (int i = tid; i < ATT_BN * 32; i += 256) {
            int row = i >> 5, c4 = (i & 31) << 2;
            size_t goff = (size_t)(k0 + row) * (3 * DMODEL) + c4;
            *(float4*)(sK + row * QSTRIDE + c4) = *(const float4*)(kbase + goff);
            *(float4*)(sV + row * QSTRIDE + c4) = *(const float4*)(vbase + goff);
        }
        __syncthreads();

        float s[16];
        #pragma unroll
        for (int jj = 0; jj < 16; jj++) s[jj] = 0.f;
        const float* qr = sQ + r * QSTRIDE;
        #pragma unroll 2
        for (int d = 0; d < HD; d += 4) {
            float4 qv = *(const float4*)(qr + d);
            #pragma unroll
            for (int jj = 0; jj < 16; jj++) {
                float4 kv = *(const float4*)(sK + (qd + (jj << 2)) * QSTRIDE + d);
                s[jj] = fmaf(qv.x, kv.x, s[jj]);
                s[jj] = fmaf(qv.y, kv.y, s[jj]);
                s[jj] = fmaf(qv.z, kv.z, s[jj]);
                s[jj] = fmaf(qv.w, kv.w, s[jj]);
            }
        }

        float tmax = -1e30f;
        #pragma unroll
        for (int jj = 0; jj < 16; jj++) {
            int jgl = k0 + qd + (jj << 2);
            s[jj] = (jgl <= qg) ? s[jj] * scale : -1e30f;
            tmax = fmaxf(tmax, s[jj]);
        }
        tmax = fmaxf(tmax, __shfl_xor_sync(0xffffffffu, tmax, 1));
        tmax = fmaxf(tmax, __shfl_xor_sync(0xffffffffu, tmax, 2));

        float mnew = fmaxf(mrow, tmax);
        float corr = __expf(mrow - mnew);
        float psum = 0.f;
        #pragma unroll
        for (int jj = 0; jj < 16; jj++) {
            float p = __expf(s[jj] - mnew);
            s[jj] = p;
            psum += p;
        }
        psum += __shfl_xor_sync(0xffffffffu, psum, 1);
        psum += __shfl_xor_sync(0xffffffffu, psum, 2);
        lrow = lrow * corr + psum;
        mrow = mnew;
        #pragma unroll
        for (int i = 0; i < 32; i++) accO[i] *= corr;

        #pragma unroll
        for (int jj = 0; jj < 16; jj++)
            sP[r * PSTRIDE + qd + (jj << 2)] = s[jj];
        __syncthreads();

        const float* prow = sP + r * PSTRIDE;
        #pragma unroll 4
        for (int j = 0; j < ATT_BN; j++) {
            float p = prow[j];
            const float4* vr = (const float4*)(sV + j * QSTRIDE + (qd << 5));
            #pragma unroll
            for (int cc = 0; cc < 8; cc++) {
                float4 vv = vr[cc];
                accO[cc * 4 + 0] = fmaf(p, vv.x, accO[cc * 4 + 0]);
                accO[cc * 4 + 1] = fmaf(p, vv.y, accO[cc * 4 + 1]);
                accO[cc * 4 + 2] = fmaf(p, vv.z, accO[cc * 4 + 2]);
                accO[cc * 4 + 3] = fmaf(p, vv.w, accO[cc * 4 + 3]);
            }
        }
    }

    float inv = 1.f / lrow;
    size_t base = (size_t)(b * LSEQ + qg) * DMODEL + h * HD + (qd << 5);
    __half2* oh2 = (__half2*)(Oh + base);
    __half2* ol2 = (__half2*)(Ol + base);
    #pragma unroll
    for (int cc = 0; cc < 16; cc++) {
        float w0 = accO[cc * 2] * inv;
        float w1 = accO[cc * 2 + 1] * inv;
        __half h0 = hf_hi(w0), h1 = hf_hi(w1);
        __half2 hh; hh.x = h0; hh.y = h1;
        __half2 ll; ll.x = hf_lo(w0, h0); ll.y = hf_lo(w1, h1);
        oh2[cc] = hh; ol2[cc] = ll;
    }
}

// ---------------------------------------------------------------------------
// SwiGLU -> fp16 hi/lo  (per-float4 of the OUTPUT: ROWS*4*DMODEL elements)
// ---------------------------------------------------------------------------
__global__ void __launch_bounds__(256)
swiglu_split(const float* __restrict__ P,
             __half* __restrict__ Fh, __half* __restrict__ Fl)
{
    size_t i4 = (size_t)blockIdx.x * 256 + threadIdx.x;  // output float4 index
    if (i4 >= (size_t)ROWS * 4 * DMODEL / 4) return;
    size_t rr  = i4 >> 11;       // 2048 float4 per 8192-wide output row
    size_t kk4 = i4 & 2047;
    const float4 gt = *(const float4*)(P + rr * 16384 + kk4 * 4);
    const float4 vl = *(const float4*)(P + rr * 16384 + 8192 + kk4 * 4);
    float f[4];
    f[0] = gt.x / (1.f + __expf(-gt.x)) * vl.x;
    f[1] = gt.y / (1.f + __expf(-gt.y)) * vl.y;
    f[2] = gt.z / (1.f + __expf(-gt.z)) * vl.z;
    f[3] = gt.w / (1.f + __expf(-gt.w)) * vl.w;
    size_t ob = rr * 8192 + kk4 * 4;
    __half2* fh2 = (__half2*)(Fh + ob);
    __half2* fl2 = (__half2*)(Fl + ob);
    #pragma unroll
    for (int p = 0; p < 2; p++) {
        __half h0 = hf_hi(f[p*2]), h1 = hf_hi(f[p*2+1]);
        __half2 hh; hh.x = h0; hh.y = h1;
        __half2 ll; ll.x = hf_lo(f[p*2], h0); ll.y = hf_lo(f[p*2+1], h1);
        fh2[p] = hh; fl2[p] = ll;
    }
}

// ---------------------------------------------------------------------------
// Host launcher
// ---------------------------------------------------------------------------
extern "C" void kernel_launch(void* const* d_in, const int* in_sizes, int n_in,
                              void* d_out, int out_size)
{
    const float* x    = (const float*)d_in[0];
    const float* Wqkv = (const float*)d_in[1];
    const float* bqkv = (const float*)d_in[2];
    const float* Wo   = (const float*)d_in[3];
    const float* bo   = (const float*)d_in[4];
    const float* g1   = (const float*)d_in[5];
    const float* g2   = (const float*)d_in[6];
    const float* Wp   = (const float*)d_in[7];
    const float* bp   = (const float*)d_in[8];
    const float* Wff  = (const float*)d_in[9];
    const float* bff  = (const float*)d_in[10];
    float* out = (float*)d_out;

    float *p_qkv, *p_x2, *p_p;
    __half *p_xnh, *p_xnl, *p_oh, *p_ol, *p_ffh, *p_ffl;
    __half *p_wqkvh, *p_woh, *p_wph, *p_wffh;
    cudaGetSymbolAddress((void**)&p_qkv, g_qkv);
    cudaGetSymbolAddress((void**)&p_x2,  g_x2);
    cudaGetSymbolAddress((void**)&p_p,   g_p);
    cudaGetSymbolAddress((void**)&p_xnh, g_xnh);  cudaGetSymbolAddress((void**)&p_xnl, g_xnl);
    cudaGetSymbolAddress((void**)&p_oh,  g_oh);   cudaGetSymbolAddress((void**)&p_ol,  g_ol);
    cudaGetSymbolAddress((void**)&p_ffh, g_ffh);  cudaGetSymbolAddress((void**)&p_ffl, g_ffl);
    cudaGetSymbolAddress((void**)&p_wqkvh, g_wqkvh);
    cudaGetSymbolAddress((void**)&p_woh, g_woh);
    cudaGetSymbolAddress((void**)&p_wph, g_wph);
    cudaGetSymbolAddress((void**)&p_wffh, g_wffh);

    cudaFuncSetAttribute(attn_kernel, cudaFuncAttributeMaxDynamicSharedMemorySize, ATT_SMEM);
    cudaFuncSetAttribute(gemm_kernel, cudaFuncAttributeMaxDynamicSharedMemorySize, GSMEM);

    // Weight transposition (fp16 hi only)
    transp_half<<<dim3(3 * DMODEL / 32, DMODEL / 32), 256>>>(Wqkv, p_wqkvh, DMODEL, 3 * DMODEL);
    transp_half<<<dim3(DMODEL / 32, DMODEL / 32), 256>>>(Wo, p_woh, DMODEL, DMODEL);
    transp_half<<<dim3(8 * DMODEL / 32, DMODEL / 32), 256>>>(Wp, p_wph, DMODEL, 8 * DMODEL);
    transp_half<<<dim3(DMODEL / 32, 4 * DMODEL / 32), 256>>>(Wff, p_wffh, 4 * DMODEL, DMODEL);

    // 1. pre-norm (-> fp16 split)
    rmsnorm_split<<<ROWS, 256>>>(x, g1, p_xnh, p_xnl);

    // 2. QKV projection
    gemm_kernel<<<dim3(3 * DMODEL / 128, ROWS / 128), 512, GSMEM>>>(
        p_xnh, p_xnl, p_wqkvh, bqkv, nullptr, p_qkv, DMODEL, 3 * DMODEL);

    // 3. RoPE
    rope_kernel<<<(ROWS * NH * 64) / 256, 256>>>(p_qkv);

    // 4. causal flash attention (-> fp16 split)
    attn_kernel<<<dim3(LSEQ / ATT_BM, BD * NH), 256, ATT_SMEM>>>(p_qkv, p_oh, p_ol);

    // 5. output projection + residual
    gemm_kernel<<<dim3(DMODEL / 128, ROWS / 128), 512, GSMEM>>>(
        p_oh, p_ol, p_woh, bo, x, p_x2, DMODEL, DMODEL);

    // 6. second pre-norm (-> fp16 split)
    rmsnorm_split<<<ROWS, 256>>>(p_x2, g2, p_xnh, p_xnl);

    // 7. FFN up-projection
    gemm_kernel<<<dim3(8 * DMODEL / 128, ROWS / 128), 512, GSMEM>>>(
        p_xnh, p_xnl, p_wph, bp, nullptr, p_p, DMODEL, 8 * DMODEL);

    // 8. SwiGLU (-> fp16 split)
    swiglu_split<<<(ROWS * 4 * DMODEL / 4) / 256, 256>>>(p_p, p_ffh, p_ffl);

    // 9. FFN down-projection + residual -> output
    gemm_kernel<<<dim3(DMODEL / 128, ROWS / 128), 512, GSMEM>>>(
        p_ffh, p_ffl, p_wffh, bff, p_x2, out, 4 * DMODEL, DMODEL);
}

// round 11
// speedup vs baseline: 2.3903x; 1.1895x over previous
#include <cuda_runtime.h>
#include <cuda_fp16.h>
#include <math.h>
#include <stdint.h>

// ---------------------------------------------------------------------------
// Problem constants
// ---------------------------------------------------------------------------
#define BD      2
#define LSEQ    2048
#define DMODEL  2048
#define NH      16
#define HD      128
#define ROWS    (BD * LSEQ)      // 4096

// ---------------------------------------------------------------------------
// Scratch (device globals -- no allocation allowed)
// ---------------------------------------------------------------------------
__device__ float g_qkv[ROWS * 3 * DMODEL];                 // fp32
__device__ float g_x2 [ROWS * DMODEL];
__device__ float g_p  [(size_t)ROWS * 8 * DMODEL];

__device__ __half g_xn [ROWS * DMODEL];
__device__ __half g_o  [ROWS * DMODEL];
__device__ __half g_ff [(size_t)ROWS * 4 * DMODEL];
// transposed weights [N, K] fp16
__device__ __half g_wqkv[3 * DMODEL * DMODEL];
__device__ __half g_wo  [DMODEL * DMODEL];
__device__ __half g_wp  [(size_t)8 * DMODEL * DMODEL];
__device__ __half g_wff [(size_t)4 * DMODEL * DMODEL];

// ---------------------------------------------------------------------------
// Helpers
// ---------------------------------------------------------------------------
__device__ __forceinline__ uint32_t smem_u32(const void* p) {
    uint32_t a;
    asm("{ .reg .u64 t; cvta.to.shared.u64 t, %1; cvt.u32.u64 %0, t; }"
        : "=r"(a) : "l"(p));
    return a;
}
__device__ __forceinline__ void cp16(uint32_t dst, const void* src) {
    asm volatile("cp.async.cg.shared.global [%0], [%1], 16;" :: "r"(dst), "l"(src));
}
__device__ __forceinline__ void ldsm_x4(uint32_t* r, uint32_t a) {
    asm volatile("ldmatrix.sync.aligned.m8n8.x4.shared.b16 {%0,%1,%2,%3}, [%4];"
        : "=r"(r[0]), "=r"(r[1]), "=r"(r[2]), "=r"(r[3]) : "r"(a));
}
__device__ __forceinline__ void ldsm_x2(uint32_t* r, uint32_t a) {
    asm volatile("ldmatrix.sync.aligned.m8n8.x2.shared.b16 {%0,%1}, [%2];"
        : "=r"(r[0]), "=r"(r[1]) : "r"(a));
}
__device__ __forceinline__ void mma_f32(float* d, const uint32_t* a, const uint32_t* b) {
    asm volatile("mma.sync.aligned.m16n8k16.row.col.f32.f16.f16.f32 "
        "{%0,%1,%2,%3}, {%4,%5,%6,%7}, {%8,%9}, {%0,%1,%2,%3};"
        : "+f"(d[0]), "+f"(d[1]), "+f"(d[2]), "+f"(d[3])
        : "r"(a[0]), "r"(a[1]), "r"(a[2]), "r"(a[3]), "r"(b[0]), "r"(b[1]));
}

// ---------------------------------------------------------------------------
// fp16 mma GEMM (single pass): C[M,N] = A[M,K] @ B[N,K]^T + bias (+res)
// fp32 accumulation. CTA 128x128, 16 warps (4x4), warp tile 32x32,
// 512 threads (4 warps/SMSP). K-chunk 32, 4-stage cp.async (80KB smem),
// one syncthreads per chunk. Pitch 40 fp16 (80B): ldmatrix conflict-free.
// ---------------------------------------------------------------------------
#define GK       32
#define APITCH_B 80
#define COMP_B   10240            // 128 * 80
#define STAGE_B  20480            // A, B
#define NSTAGE   4
#define GSMEM    (NSTAGE * STAGE_B)   // 81920

__device__ __forceinline__ void g_load_chunk(
    uint32_t st, int c, int tid,
    const __half* __restrict__ A, const __half* __restrict__ B,
    int K, int m0, int n0)
{
    const int k0 = c * GK;
    // 512 threads: each loads one 16B chunk of each array
    int r = tid >> 2, cc = tid & 3;      // row 0..127, 16B chunk in 64B row
    uint32_t so = (uint32_t)(r * APITCH_B + cc * 16);
    cp16(st + so,          A + (size_t)(m0 + r) * K + k0 + cc * 8);
    cp16(st + COMP_B + so, B + (size_t)(n0 + r) * K + k0 + cc * 8);
    asm volatile("cp.async.commit_group;" ::: "memory");
}

__global__ void __launch_bounds__(512)
gemm_kernel(const __half* __restrict__ A, const __half* __restrict__ B,
            const float* __restrict__ bias, const float* __restrict__ res,
            float* __restrict__ C, int K, int N)
{
    extern __shared__ __align__(16) char sm_[];
    const uint32_t sb = smem_u32(sm_);
    const int tid  = threadIdx.x;
    const int lane = tid & 31;
    const int wid  = tid >> 5;          // 0..15
    const int wm   = wid >> 2;          // 0..3
    const int wn   = wid & 3;           // 0..3
    const int m0 = blockIdx.y << 7;
    const int n0 = blockIdx.x << 7;
    const int NC = K / GK;

    float acc[2][4][4];
    #pragma unroll
    for (int i = 0; i < 2; i++)
        #pragma unroll
        for (int j = 0; j < 4; j++)
            #pragma unroll
            for (int q = 0; q < 4; q++) acc[i][j][q] = 0.f;

    g_load_chunk(sb,               0, tid, A, B, K, m0, n0);
    g_load_chunk(sb + STAGE_B,     1, tid, A, B, K, m0, n0);
    g_load_chunk(sb + 2 * STAGE_B, 2, tid, A, B, K, m0, n0);

    // ldmatrix per-lane source offsets (bytes)
    const int rowA  = (lane & 7) + ((lane >> 3) & 1) * 8;
    const int kaddA = (lane >> 4) * 16;
    const uint32_t a_ld = (uint32_t)((wm * 32 + rowA) * APITCH_B + kaddA);
    const int rowB  = lane & 7;
    const int kaddB = ((lane >> 3) & 1) * 16;
    const uint32_t b_ld = (uint32_t)((wn * 32 + rowB) * APITCH_B + kaddB);

    for (int c = 0; c < NC; c++) {
        asm volatile("cp.async.wait_group 2;" ::: "memory");
        __syncthreads();

        if (c + 3 < NC)
            g_load_chunk(sb + (uint32_t)((c + 3) & 3) * STAGE_B, c + 3, tid,
                         A, B, K, m0, n0);

        const uint32_t st = sb + (uint32_t)(c & 3) * STAGE_B;

        #pragma unroll
        for (int kh = 0; kh < 2; kh++) {
            const uint32_t abase = st + a_ld + kh * 32;
            const uint32_t bbase = st + COMP_B + b_ld + kh * 32;

            uint32_t ar[2][4], br[4][2];
            #pragma unroll
            for (int mt = 0; mt < 2; mt++)
                ldsm_x4(ar[mt], abase + mt * (16 * APITCH_B));
            #pragma unroll
            for (int nt = 0; nt < 4; nt++)
                ldsm_x2(br[nt], bbase + nt * (8 * APITCH_B));

            #pragma unroll
            for (int mt = 0; mt < 2; mt++)
                #pragma unroll
                for (int nt = 0; nt < 4; nt++)
                    mma_f32(acc[mt][nt], ar[mt], br[nt]);
        }
    }

    // epilogue
    #pragma unroll
    for (int mt = 0; mt < 2; mt++) {
        #pragma unroll
        for (int nt = 0; nt < 4; nt++) {
            const int rg = m0 + wm * 32 + mt * 16 + (lane >> 2);
            const int cg = n0 + wn * 32 + nt * 8 + (lane & 3) * 2;
            float2 bv = *(const float2*)(bias + cg);
            float2 o0, o1;
            o0.x = acc[mt][nt][0] + bv.x;  o0.y = acc[mt][nt][1] + bv.y;
            o1.x = acc[mt][nt][2] + bv.x;  o1.y = acc[mt][nt][3] + bv.y;
            if (res) {
                float2 r0 = *(const float2*)(res + (size_t)rg * N + cg);
                float2 r1 = *(const float2*)(res + (size_t)(rg + 8) * N + cg);
                o0.x += r0.x; o0.y += r0.y;
                o1.x += r1.x; o1.y += r1.y;
            }
            *(float2*)(C + (size_t)rg * N + cg)       = o0;
            *(float2*)(C + (size_t)(rg + 8) * N + cg) = o1;
        }
    }
}

// ---------------------------------------------------------------------------
// Weight transpose + fp16 round: W[K,N] fp32 -> Th[N,K] fp16
// ---------------------------------------------------------------------------
__global__ void __launch_bounds__(256)
transp_half(const float* __restrict__ W, __half* __restrict__ Th, int Kd, int Nd)
{
    __shared__ float t[32][33];
    const int n0 = blockIdx.x * 32, k0 = blockIdx.y * 32;
    const int tx = threadIdx.x & 31, ty = threadIdx.x >> 5;
    #pragma unroll
    for (int i = 0; i < 4; i++) {
        int kk = ty + i * 8;
        t[kk][tx] = W[(size_t)(k0 + kk) * Nd + n0 + tx];
    }
    __syncthreads();
    #pragma unroll
    for (int i = 0; i < 4; i++) {
        int nn = ty + i * 8;
        Th[(size_t)(n0 + nn) * Kd + k0 + tx] = __float2half_rn(t[tx][nn]);
    }
}

// ---------------------------------------------------------------------------
// RMSNorm -> fp16
// ---------------------------------------------------------------------------
__global__ void __launch_bounds__(256)
rmsnorm_half(const float* __restrict__ in, const float* __restrict__ g,
             __half* __restrict__ outh)
{
    __shared__ float red[8];
    const int row = blockIdx.x;
    const int tid = threadIdx.x;
    const float4* inr = (const float4*)(in + (size_t)row * DMODEL);
    float4 v0 = inr[tid];
    float4 v1 = inr[tid + 256];
    float ss = v0.x*v0.x + v0.y*v0.y + v0.z*v0.z + v0.w*v0.w
             + v1.x*v1.x + v1.y*v1.y + v1.z*v1.z + v1.w*v1.w;
    #pragma unroll
    for (int o = 16; o; o >>= 1) ss += __shfl_xor_sync(0xffffffffu, ss, o);
    if ((tid & 31) == 0) red[tid >> 5] = ss;
    __syncthreads();
    float tot = red[0]+red[1]+red[2]+red[3]+red[4]+red[5]+red[6]+red[7];
    float rs = rsqrtf(tot * (1.0f / DMODEL) + 1e-8f);

    const float4* gr = (const float4*)g;
    float4 ga = gr[tid], gb = gr[tid + 256];
    __half2* oh2 = (__half2*)(outh + (size_t)row * DMODEL);
    float y[8] = { v0.x*rs*ga.x, v0.y*rs*ga.y, v0.z*rs*ga.z, v0.w*rs*ga.w,
                   v1.x*rs*gb.x, v1.y*rs*gb.y, v1.z*rs*gb.z, v1.w*rs*gb.w };
    #pragma unroll
    for (int p = 0; p < 4; p++) {
        __half2 hh;
        hh.x = __float2half_rn(y[p*2]);
        hh.y = __float2half_rn(y[p*2+1]);
        int base = (p < 2) ? (tid*2 + p) : ((tid+256)*2 + (p-2));
        oh2[base] = hh;
    }
}

// ---------------------------------------------------------------------------
// RoPE (in place on q,k of qkv)
// ---------------------------------------------------------------------------
__global__ void __launch_bounds__(256)
rope_kernel(float* __restrict__ qkv)
{
    const long idx = (long)blockIdx.x * 256 + threadIdx.x;
    const int  i   = (int)(idx & 63);
    const int  h   = (int)((idx >> 6) & 15);
    const long bl  = idx >> 10;
    const long l   = bl & 2047;

    float freq = expf(-(float)i * 0.14391156642875464f);
    float angle = (float)l * freq;
    float s, c;
    sincosf(angle, &s, &c);

    float* qp = qkv + bl * (3 * DMODEL) + h * HD + i;
    float* kp = qp + DMODEL;
    float q1 = qp[0], q2 = qp[64];
    float k1 = kp[0], k2 = kp[64];
    qp[0]  = q1 * c - q2 * s;
    qp[64] = q2 * c + q1 * s;
    kp[0]  = k1 * c - k2 * s;
    kp[64] = k2 * c + k1 * s;
}

// ---------------------------------------------------------------------------
// Flash attention (causal, fp32), outputs fp16
// ---------------------------------------------------------------------------
#define ATT_BM   64
#define ATT_BN   64
#define QSTRIDE  132
#define PSTRIDE  68
#define ATT_SMEM ((3 * ATT_BM * QSTRIDE + ATT_BM * PSTRIDE) * (int)sizeof(float))

__global__ void __launch_bounds__(256)
attn_kernel(const float* __restrict__ qkv, __half* __restrict__ Oh)
{
    extern __shared__ float smem[];
    float* sQ = smem;
    float* sK = sQ + ATT_BM * QSTRIDE;
    float* sV = sK + ATT_BN * QSTRIDE;
    float* sP = sV + ATT_BN * QSTRIDE;

    const int bh = blockIdx.y;
    const int b  = bh >> 4;
    const int h  = bh & 15;
    const int qi = gridDim.x - 1 - blockIdx.x;
    const int q0 = qi * ATT_BM;
    const int tid = threadIdx.x;
    const int r  = tid >> 2;
    const int qd = tid & 3;

    const float* qbase = qkv + (size_t)(b * LSEQ) * (3 * DMODEL) + h * HD;
    const float* kbase = qbase + DMODEL;
    const float* vbase = qbase + 2 * DMODEL;

    for (int i = tid; i < ATT_BM * 32; i += 256) {
        int row = i >> 5, c4 = (i & 31) << 2;
        *(float4*)(sQ + row * QSTRIDE + c4) =
            *(const float4*)(qbase + (size_t)(q0 + row) * (3 * DMODEL) + c4);
    }

    float accO[32];
    #pragma unroll
    for (int i = 0; i < 32; i++) accO[i] = 0.f;
    float mrow = -1e30f, lrow = 0.f;
    const int qg = q0 + r;
    const float scale = 0.088388347648318447f;

    const int nk = qi + 1;
    for (int kt = 0; kt < nk; kt++) {
        const int k0 = kt * ATT_BN;
        __syncthreads();
        for (int i = tid; i < ATT_BN * 32; i += 256) {
            int row = i >> 5, c4 = (i & 31) << 2;
            size_t goff = (size_t)(k0 + row) * (3 * DMODEL) + c4;
            *(float4*)(sK + row * QSTRIDE + c4) = *(const float4*)(kbase + goff);
            *(float4*)(sV + row * QSTRIDE + c4) = *(const float4*)(vbase + goff);
        }
        __syncthreads();

        float s[16];
        #pragma unroll
        for (int jj = 0; jj < 16; jj++) s[jj] = 0.f;
        const float* qr = sQ + r * QSTRIDE;
        #pragma unroll 2
        for (int d = 0; d < HD; d += 4) {
            float4 qv = *(const float4*)(qr + d);
            #pragma unroll
            for (int jj = 0; jj < 16; jj++) {
                float4 kv = *(const float4*)(sK + (qd + (jj << 2)) * QSTRIDE + d);
                s[jj] = fmaf(qv.x, kv.x, s[jj]);
                s[jj] = fmaf(qv.y, kv.y, s[jj]);
                s[jj] = fmaf(qv.z, kv.z, s[jj]);
                s[jj] = fmaf(qv.w, kv.w, s[jj]);
            }
        }

        float tmax = -1e30f;
        #pragma unroll
        for (int jj = 0; jj < 16; jj++) {
            int jgl = k0 + qd + (jj << 2);
            s[jj] = (jgl <= qg) ? s[jj] * scale : -1e30f;
            tmax = fmaxf(tmax, s[jj]);
        }
        tmax = fmaxf(tmax, __shfl_xor_sync(0xffffffffu, tmax, 1));
        tmax = fmaxf(tmax, __shfl_xor_sync(0xffffffffu, tmax, 2));

        float mnew = fmaxf(mrow, tmax);
        float corr = __expf(mrow - mnew);
        float psum = 0.f;
        #pragma unroll
        for (int jj = 0; jj < 16; jj++) {
            float p = __expf(s[jj] - mnew);
            s[jj] = p;
            psum += p;
        }
        psum += __shfl_xor_sync(0xffffffffu, psum, 1);
        psum += __shfl_xor_sync(0xffffffffu, psum, 2);
        lrow = lrow * corr + psum;
        mrow = mnew;
        #pragma unroll
        for (int i = 0; i < 32; i++) accO[i] *= corr;

        #pragma unroll
        for (int jj = 0; jj < 16; jj++)
            sP[r * PSTRIDE + qd + (jj << 2)] = s[jj];
        __syncthreads();

        const float* prow = sP + r * PSTRIDE;
        #pragma unroll 4
        for (int j = 0; j < ATT_BN; j++) {
            float p = prow[j];
            const float4* vr = (const float4*)(sV + j * QSTRIDE + (qd << 5));
            #pragma unroll
            for (int cc = 0; cc < 8; cc++) {
                float4 vv = vr[cc];
                accO[cc * 4 + 0] = fmaf(p, vv.x, accO[cc * 4 + 0]);
                accO[cc * 4 + 1] = fmaf(p, vv.y, accO[cc * 4 + 1]);
                accO[cc * 4 + 2] = fmaf(p, vv.z, accO[cc * 4 + 2]);
                accO[cc * 4 + 3] = fmaf(p, vv.w, accO[cc * 4 + 3]);
            }
        }
    }

    float inv = 1.f / lrow;
    size_t base = (size_t)(b * LSEQ + qg) * DMODEL + h * HD + (qd << 5);
    __half2* oh2 = (__half2*)(Oh + base);
    #pragma unroll
    for (int cc = 0; cc < 16; cc++) {
        __half2 hh;
        hh.x = __float2half_rn(accO[cc * 2] * inv);
        hh.y = __float2half_rn(accO[cc * 2 + 1] * inv);
        oh2[cc] = hh;
    }
}

// ---------------------------------------------------------------------------
// SwiGLU -> fp16  (per-float4 of the OUTPUT: ROWS*4*DMODEL elements)
// ---------------------------------------------------------------------------
__global__ void __launch_bounds__(256)
swiglu_half(const float* __restrict__ P, __half* __restrict__ Fh)
{
    size_t i4 = (size_t)blockIdx.x * 256 + threadIdx.x;  // output float4 index
    if (i4 >= (size_t)ROWS * 4 * DMODEL / 4) return;
    size_t rr  = i4 >> 11;       // 2048 float4 per 8192-wide output row
    size_t kk4 = i4 & 2047;
    const float4 gt = *(const float4*)(P + rr * 16384 + kk4 * 4);
    const float4 vl = *(const float4*)(P + rr * 16384 + 8192 + kk4 * 4);
    float f[4];
    f[0] = gt.x / (1.f + __expf(-gt.x)) * vl.x;
    f[1] = gt.y / (1.f + __expf(-gt.y)) * vl.y;
    f[2] = gt.z / (1.f + __expf(-gt.z)) * vl.z;
    f[3] = gt.w / (1.f + __expf(-gt.w)) * vl.w;
    size_t ob = rr * 8192 + kk4 * 4;
    __half2* fh2 = (__half2*)(Fh + ob);
    #pragma unroll
    for (int p = 0; p < 2; p++) {
        __half2 hh;
        hh.x = __float2half_rn(f[p*2]);
        hh.y = __float2half_rn(f[p*2+1]);
        fh2[p] = hh;
    }
}

// ---------------------------------------------------------------------------
// Host launcher
// ---------------------------------------------------------------------------
extern "C" void kernel_launch(void* const* d_in, const int* in_sizes, int n_in,
                              void* d_out, int out_size)
{
    const float* x    = (const float*)d_in[0];
    const float* Wqkv = (const float*)d_in[1];
    const float* bqkv = (const float*)d_in[2];
    const float* Wo   = (const float*)d_in[3];
    const float* bo   = (const float*)d_in[4];
    const float* g1   = (const float*)d_in[5];
    const float* g2   = (const float*)d_in[6];
    const float* Wp   = (const float*)d_in[7];
    const float* bp   = (const float*)d_in[8];
    const float* Wff  = (const float*)d_in[9];
    const float* bff  = (const float*)d_in[10];
    float* out = (float*)d_out;

    float *p_qkv, *p_x2, *p_p;
    __half *p_xn, *p_o, *p_ff;
    __half *p_wqkv, *p_wo, *p_wp, *p_wff;
    cudaGetSymbolAddress((void**)&p_qkv, g_qkv);
    cudaGetSymbolAddress((void**)&p_x2,  g_x2);
    cudaGetSymbolAddress((void**)&p_p,   g_p);
    cudaGetSymbolAddress((void**)&p_xn,  g_xn);
    cudaGetSymbolAddress((void**)&p_o,   g_o);
    cudaGetSymbolAddress((void**)&p_ff,  g_ff);
    cudaGetSymbolAddress((void**)&p_wqkv, g_wqkv);
    cudaGetSymbolAddress((void**)&p_wo,   g_wo);
    cudaGetSymbolAddress((void**)&p_wp,   g_wp);
    cudaGetSymbolAddress((void**)&p_wff,  g_wff);

    cudaFuncSetAttribute(attn_kernel, cudaFuncAttributeMaxDynamicSharedMemorySize, ATT_SMEM);
    cudaFuncSetAttribute(gemm_kernel, cudaFuncAttributeMaxDynamicSharedMemorySize, GSMEM);

    // Weight transposition (fp16)
    transp_half<<<dim3(3 * DMODEL / 32, DMODEL / 32), 256>>>(Wqkv, p_wqkv, DMODEL, 3 * DMODEL);
    transp_half<<<dim3(DMODEL / 32, DMODEL / 32), 256>>>(Wo, p_wo, DMODEL, DMODEL);
    transp_half<<<dim3(8 * DMODEL / 32, DMODEL / 32), 256>>>(Wp, p_wp, DMODEL, 8 * DMODEL);
    transp_half<<<dim3(DMODEL / 32, 4 * DMODEL / 32), 256>>>(Wff, p_wff, 4 * DMODEL, DMODEL);

    // 1. pre-norm (-> fp16)
    rmsnorm_half<<<ROWS, 256>>>(x, g1, p_xn);

    // 2. QKV projection
    gemm_kernel<<<dim3(3 * DMODEL / 128, ROWS / 128), 512, GSMEM>>>(
        p_xn, p_wqkv, bqkv, nullptr, p_qkv, DMODEL, 3 * DMODEL);

    // 3. RoPE
    rope_kernel<<<(ROWS * NH * 64) / 256, 256>>>(p_qkv);

    // 4. causal flash attention (-> fp16)
    attn_kernel<<<dim3(LSEQ / ATT_BM, BD * NH), 256, ATT_SMEM>>>(p_qkv, p_o);

    // 5. output projection + residual
    gemm_kernel<<<dim3(DMODEL / 128, ROWS / 128), 512, GSMEM>>>(
        p_o, p_wo, bo, x, p_x2, DMODEL, DMODEL);

    // 6. second pre-norm (-> fp16)
    rmsnorm_half<<<ROWS, 256>>>(p_x2, g2, p_xn);

    // 7. FFN up-projection
    gemm_kernel<<<dim3(8 * DMODEL / 128, ROWS / 128), 512, GSMEM>>>(
        p_xn, p_wp, bp, nullptr, p_p, DMODEL, 8 * DMODEL);

    // 8. SwiGLU (-> fp16)
    swiglu_half<<<(ROWS * 4 * DMODEL / 4) / 256, 256>>>(p_p, p_ff);

    // 9. FFN down-projection + residual -> output
    gemm_kernel<<<dim3(DMODEL / 128, ROWS / 128), 512, GSMEM>>>(
        p_ff, p_wff, bff, p_x2, out, 4 * DMODEL, DMODEL);
}